// round 2
// baseline (speedup 1.0000x reference)
#include <cuda_runtime.h>
#include <cstdint>

// Shapes (fixed for this problem)
#define B_ 4096
#define N_ 64
#define D_ 512
#define H_ 2
#define DK_ 256

// ---------------- scratch (static device arrays; no allocs) ----------------
__device__ __align__(16) float g_Ck[512 * 1024];            // [D, H*D]  Wq_h @ Wk_h^T / 16
__device__ __align__(16) float g_Cv[1024 * 512];            // [H*D, D]  Wv_h @ Wo_hrows
__device__ __align__(16) float g_QT[(size_t)B_ * 1024];     // src @ Ck
__device__ __align__(16) float g_CTX[(size_t)B_ * 1024];    // attn @ seq (per head, concat)
__device__ __align__(16) float g_PROJ[(size_t)B_ * 512];
__device__ __align__(16) float g_LN[(size_t)B_ * 512];
__device__ __align__(16) float g_H1[(size_t)B_ * 512];
__device__ int g_mask_word;   // 1 = 4-byte mask elements, 0 = 1-byte

// ---------------- mask dtype detection ----------------
// bool may arrive as uint8, int32, or float32. For 4-byte carriers every word
// is 0, 1, or 0x3F800000. For a byte carrier, words mix bytes (e.g. 0x00010001)
// which fall outside that set with overwhelming probability over 256 samples.
__global__ void detect_mask_kernel(const unsigned int* __restrict__ m)
{
    __shared__ int bad;
    if (threadIdx.x == 0) bad = 0;
    __syncthreads();
    unsigned int w = m[threadIdx.x];
    if (!(w == 0u || w == 1u || w == 0x3F800000u)) atomicOr(&bad, 1);
    __syncthreads();
    if (threadIdx.x == 0) g_mask_word = bad ? 0 : 1;
}

// ---------------- generic fp32 tiled GEMM: C = alpha*A@B (+C)(+bias)(+resid)(relu) ----
#define FLAG_BIAS  1
#define FLAG_RELU  2
#define FLAG_RESID 4
#define FLAG_ACCUM 8

__global__ __launch_bounds__(256, 2)
void gemm_f32(const float* __restrict__ A, int lda_m, int lda_k,
              const float* __restrict__ Bm, int ldb_k, int ldb_n,
              float* __restrict__ C, int ldc,
              const float* __restrict__ bias,
              const float* __restrict__ resid, int ldr,
              int K, float alpha, int flags)
{
    __shared__ float As[8][128];
    __shared__ float Bs[8][128];
    const int tid = threadIdx.x;
    const int bm = blockIdx.y * 128;
    const int bn = blockIdx.x * 128;
    const int tx = tid & 15, ty = tid >> 4;

    float acc[8][8];
#pragma unroll
    for (int i = 0; i < 8; i++)
#pragma unroll
        for (int j = 0; j < 8; j++) acc[i][j] = 0.f;

    const int am  = tid >> 1;         // 0..127
    const int akq = (tid & 1) * 4;    // 0 or 4
    const int bk  = tid >> 5;         // 0..7
    const int bnq = (tid & 31) * 4;   // 0..124

    for (int k0 = 0; k0 < K; k0 += 8) {
        if (lda_k == 1) {
            float4 v = *(const float4*)(A + (size_t)(bm + am) * lda_m + k0 + akq);
            As[akq + 0][am] = v.x; As[akq + 1][am] = v.y;
            As[akq + 2][am] = v.z; As[akq + 3][am] = v.w;
        } else {
#pragma unroll
            for (int j = 0; j < 4; j++)
                As[akq + j][am] = A[(size_t)(bm + am) * lda_m + (size_t)(k0 + akq + j) * lda_k];
        }
        if (ldb_n == 1) {
            *(float4*)&Bs[bk][bnq] = *(const float4*)(Bm + (size_t)(k0 + bk) * ldb_k + bn + bnq);
        } else {
#pragma unroll
            for (int j = 0; j < 4; j++)
                Bs[bk][bnq + j] = Bm[(size_t)(k0 + bk) * ldb_k + (size_t)(bn + bnq + j) * ldb_n];
        }
        __syncthreads();
#pragma unroll
        for (int kk = 0; kk < 8; kk++) {
            float a[8], b[8];
            *(float4*)(a)     = *(const float4*)&As[kk][ty * 8];
            *(float4*)(a + 4) = *(const float4*)&As[kk][ty * 8 + 4];
            *(float4*)(b)     = *(const float4*)&Bs[kk][tx * 8];
            *(float4*)(b + 4) = *(const float4*)&Bs[kk][tx * 8 + 4];
#pragma unroll
            for (int i = 0; i < 8; i++)
#pragma unroll
                for (int j = 0; j < 8; j++)
                    acc[i][j] += a[i] * b[j];
        }
        __syncthreads();
    }

#pragma unroll
    for (int i = 0; i < 8; i++) {
        const int row = bm + ty * 8 + i;
        float* crow = C + (size_t)row * ldc + bn + tx * 8;
        const float* rrow = (flags & FLAG_RESID) ? (resid + (size_t)row * ldr + bn + tx * 8) : nullptr;
#pragma unroll
        for (int j = 0; j < 8; j++) {
            float v = acc[i][j] * alpha;
            if (flags & FLAG_ACCUM) v += crow[j];
            if (flags & FLAG_BIAS)  v += bias[bn + tx * 8 + j];
            if (flags & FLAG_RESID) v += rrow[j];
            if (flags & FLAG_RELU)  v = fmaxf(v, 0.f);
            crow[j] = v;
        }
    }
}

// ---------------- fused attention: scores, softmax, weight-out, ctx ----------------
__global__ __launch_bounds__(256, 1)
void attention_kernel(const float* __restrict__ seq,
                      const void* __restrict__ mask,
                      const float* __restrict__ qt,   // [B,1024]
                      float* __restrict__ ctx,        // [B,1024]
                      float* __restrict__ wout)       // [B,64]
{
    extern __shared__ float s_seq[];   // 64*512
    __shared__ float s_qt[1024];
    __shared__ float s_sc[128];
    __shared__ float s_attn[128];
    __shared__ unsigned char s_mask[64];

    const int b = blockIdx.x, tid = threadIdx.x;
    const int warp = tid >> 5, lane = tid & 31;

    { // load seq tile + qt row + mask
        const float4* g = (const float4*)(seq + (size_t)b * N_ * D_);
        float4* s4 = (float4*)s_seq;
#pragma unroll 4
        for (int i = tid; i < N_ * D_ / 4; i += 256) s4[i] = g[i];
        const float4* gq = (const float4*)(qt + (size_t)b * 1024);
        ((float4*)s_qt)[tid] = gq[tid];
        if (tid < 64) {
            const int mode = g_mask_word;
            unsigned int mv;
            if (mode) mv = ((const unsigned int*)mask)[(size_t)b * N_ + tid];
            else      mv = ((const unsigned char*)mask)[(size_t)b * N_ + tid];
            s_mask[tid] = (mv != 0u) ? 1 : 0;
        }
    }
    __syncthreads();

    // 128 dot products (h,k), warp-per-dot
    for (int p = warp; p < 128; p += 8) {
        const int h = p >> 6, k = p & 63;
        const float* srow = s_seq + k * D_;
        const float* qrow = s_qt + h * D_;
        float acc = 0.f;
#pragma unroll
        for (int i = 0; i < 16; i++) acc += srow[lane + 32 * i] * qrow[lane + 32 * i];
#pragma unroll
        for (int o = 16; o; o >>= 1) acc += __shfl_xor_sync(0xffffffffu, acc, o);
        if (lane == 0) s_sc[p] = s_mask[k] ? -1e10f : acc;
    }
    __syncthreads();

    // softmax per head (warp 0 -> head 0, warp 1 -> head 1)
    if (warp < 2) {
        const int h = warp;
        float v0 = s_sc[h * 64 + lane], v1 = s_sc[h * 64 + 32 + lane];
        float m = fmaxf(v0, v1);
#pragma unroll
        for (int o = 16; o; o >>= 1) m = fmaxf(m, __shfl_xor_sync(0xffffffffu, m, o));
        float e0 = __expf(v0 - m), e1 = __expf(v1 - m);
        float s = e0 + e1;
#pragma unroll
        for (int o = 16; o; o >>= 1) s += __shfl_xor_sync(0xffffffffu, s, o);
        float inv = 1.f / s;
        s_attn[h * 64 + lane]      = e0 * inv;
        s_attn[h * 64 + 32 + lane] = e1 * inv;
    }
    __syncthreads();

    if (tid < 64) wout[(size_t)b * 64 + tid] = 0.5f * (s_attn[tid] + s_attn[64 + tid]);

    // ctx[h,d] = sum_k attn[h,k] * seq[k,d]
    float acc[4] = {0.f, 0.f, 0.f, 0.f};
    for (int k = 0; k < 64; k++) {
        const float* srow = s_seq + k * D_;
        const float a0 = s_attn[k], a1 = s_attn[64 + k];
        acc[0] += a0 * srow[tid];
        acc[1] += a0 * srow[tid + 256];
        acc[2] += a1 * srow[tid];
        acc[3] += a1 * srow[tid + 256];
    }
    float* orow = ctx + (size_t)b * 1024;
    orow[tid]       = acc[0];
    orow[tid + 256] = acc[1];
    orow[tid + 512] = acc[2];
    orow[tid + 768] = acc[3];
}

// ---------------- layernorm ----------------
__global__ __launch_bounds__(128)
void ln_kernel(const float* __restrict__ x, const float* __restrict__ gam,
               const float* __restrict__ bet, float* __restrict__ y)
{
    const int b = blockIdx.x, tid = threadIdx.x;
    const float* row = x + (size_t)b * 512;
    float v[4]; float s = 0.f;
#pragma unroll
    for (int j = 0; j < 4; j++) { v[j] = row[tid + 128 * j]; s += v[j]; }
    __shared__ float red[4];
#pragma unroll
    for (int o = 16; o; o >>= 1) s += __shfl_xor_sync(0xffffffffu, s, o);
    if ((tid & 31) == 0) red[tid >> 5] = s;
    __syncthreads();
    s = red[0] + red[1] + red[2] + red[3];
    const float mu = s * (1.f / 512.f);
    float var = 0.f;
#pragma unroll
    for (int j = 0; j < 4; j++) { float d = v[j] - mu; var += d * d; }
    __syncthreads();
#pragma unroll
    for (int o = 16; o; o >>= 1) var += __shfl_xor_sync(0xffffffffu, var, o);
    if ((tid & 31) == 0) red[tid >> 5] = var;
    __syncthreads();
    var = (red[0] + red[1] + red[2] + red[3]) * (1.f / 512.f);
    const float rs = rsqrtf(var + 1e-5f);
#pragma unroll
    for (int j = 0; j < 4; j++) {
        const int c = tid + 128 * j;
        y[(size_t)b * 512 + c] = gam[c] * (v[j] - mu) * rs + bet[c];
    }
}

// ---------------- launch ----------------
extern "C" void kernel_launch(void* const* d_in, const int* in_sizes, int n_in,
                              void* d_out, int out_size)
{
    const float* src  = (const float*)d_in[0];
    const float* seq  = (const float*)d_in[1];
    const void*  mask = d_in[2];
    const float* Wq   = (const float*)d_in[3];
    const float* Wk   = (const float*)d_in[4];
    const float* Wv   = (const float*)d_in[5];
    const float* Wo   = (const float*)d_in[6];
    const float* bo   = (const float*)d_in[7];
    const float* ln_g = (const float*)d_in[8];
    const float* ln_b = (const float*)d_in[9];
    const float* W1   = (const float*)d_in[10];
    const float* b1   = (const float*)d_in[11];
    const float* W2   = (const float*)d_in[12];
    const float* b2   = (const float*)d_in[13];
    float* y    = (float*)d_out;                       // [B, 512]
    float* wout = (float*)d_out + (size_t)B_ * 512;    // [B, 64]

    float *Ck, *Cv, *QT, *CTX, *PROJ, *LN, *H1;
    cudaGetSymbolAddress((void**)&Ck,   g_Ck);
    cudaGetSymbolAddress((void**)&Cv,   g_Cv);
    cudaGetSymbolAddress((void**)&QT,   g_QT);
    cudaGetSymbolAddress((void**)&CTX,  g_CTX);
    cudaGetSymbolAddress((void**)&PROJ, g_PROJ);
    cudaGetSymbolAddress((void**)&LN,   g_LN);
    cudaGetSymbolAddress((void**)&H1,   g_H1);

    cudaFuncSetAttribute(attention_kernel,
                         cudaFuncAttributeMaxDynamicSharedMemorySize, N_ * D_ * 4);

    dim3 blk(256);

    detect_mask_kernel<<<1, 256>>>((const unsigned int*)mask);

    // Precompute Ck_h = Wq_h @ Wk_h^T / 16  ->  g_Ck[i, h*512+d]
    for (int h = 0; h < 2; h++)
        gemm_f32<<<dim3(4, 4), blk>>>(Wq + h * 256, 512, 1,
                                      Wk + h * 256, 1, 512,
                                      Ck + h * 512, 1024,
                                      nullptr, nullptr, 0,
                                      256, 1.f / 16.f, 0);
    // Precompute Cv_h = Wv_h @ Wo[hrows,:]  ->  g_Cv[h*512+i, d]
    for (int h = 0; h < 2; h++)
        gemm_f32<<<dim3(4, 4), blk>>>(Wv + h * 256, 512, 1,
                                      Wo + (size_t)h * 256 * 512, 512, 1,
                                      Cv + (size_t)h * 512 * 512, 512,
                                      nullptr, nullptr, 0,
                                      256, 1.f, 0);
    // QT = src @ Ck   (4096 x 1024, K=512)
    gemm_f32<<<dim3(8, 32), blk>>>(src, 512, 1, Ck, 1024, 1, QT, 1024,
                                   nullptr, nullptr, 0, 512, 1.f, 0);
    // Attention
    attention_kernel<<<B_, 256, N_ * D_ * 4>>>(seq, mask, QT, CTX, wout);
    // PROJ = CTX @ Cv + bo + src
    gemm_f32<<<dim3(4, 32), blk>>>(CTX, 1024, 1, Cv, 512, 1, PROJ, 512,
                                   bo, src, 512, 1024, 1.f, FLAG_BIAS | FLAG_RESID);
    // LayerNorm
    ln_kernel<<<B_, 128>>>(PROJ, ln_g, ln_b, LN);
    // H1 = relu(LN @ W1_top + src @ W1_bot + b1)
    gemm_f32<<<dim3(4, 32), blk>>>(LN, 512, 1, W1, 512, 1, H1, 512,
                                   nullptr, nullptr, 0, 512, 1.f, 0);
    gemm_f32<<<dim3(4, 32), blk>>>(src, 512, 1, W1 + (size_t)512 * 512, 512, 1, H1, 512,
                                   b1, nullptr, 0, 512, 1.f,
                                   FLAG_ACCUM | FLAG_BIAS | FLAG_RELU);
    // y = H1 @ W2 + b2
    gemm_f32<<<dim3(4, 32), blk>>>(H1, 512, 1, W2, 512, 1, y, 512,
                                   b2, nullptr, 0, 512, 1.f, FLAG_BIAS);
}

// round 4
// speedup vs baseline: 2.0994x; 2.0994x over previous
#include <cuda_runtime.h>
#include <cstdint>

// Shapes (fixed for this problem)
#define B_ 4096
#define N_ 64
#define D_ 512
#define H_ 2
#define DK_ 256

// ---------------- scratch (static device arrays; no allocs) ----------------
__device__ __align__(16) float g_Ck[512 * 1024];            // [D, H*D]  Wq_h @ Wk_h^T / 16
__device__ __align__(16) float g_Cv[1024 * 512];            // [H*D, D]  Wv_h @ Wo_hrows
__device__ __align__(16) float g_QT[(size_t)B_ * 1024];     // src @ Ck
__device__ __align__(16) float g_CTX[(size_t)B_ * 1024];    // attn @ seq (per head, concat)
__device__ __align__(16) float g_PROJ[(size_t)B_ * 512];
__device__ __align__(16) float g_LN[(size_t)B_ * 512];
__device__ __align__(16) float g_H1[(size_t)B_ * 512];
__device__ int g_mask_word;   // 1 = 4-byte mask elements, 0 = 1-byte

// ---------------- mask dtype detection ----------------
__global__ void detect_mask_kernel(const unsigned int* __restrict__ m)
{
    __shared__ int bad;
    if (threadIdx.x == 0) bad = 0;
    __syncthreads();
    unsigned int w = m[threadIdx.x];
    if (!(w == 0u || w == 1u || w == 0x3F800000u)) atomicOr(&bad, 1);
    __syncthreads();
    if (threadIdx.x == 0) g_mask_word = bad ? 0 : 1;
}

// ---------------- tf32 tensor-core GEMM ----------------
// C[M,N] = alpha * A@B (+bias)(+resid)(relu). Tiles 128x128x32, 256 thr,
// 8 warps (2m x 4n), warp tile 64x32 via mma.m16n8k8 tf32.
// A row-major (lda). Optional split-A: rows come from A for k<ksplit, A2 after.
// B: transb=0 -> B[k,n]=Bm[k*ldb+n] ; transb=1 -> B[k,n]=Bm[n*ldb+k].
#define FLAG_BIAS  1
#define FLAG_RELU  2
#define FLAG_RESID 4

__device__ __forceinline__ uint32_t f2tf32(float f)
{
    uint32_t r;
    asm("cvt.rna.tf32.f32 %0, %1;" : "=r"(r) : "f"(f));
    return r;
}

__global__ __launch_bounds__(256)
void gemm_tf32(const float* __restrict__ A, int lda,
               const float* __restrict__ A2, int lda2, int ksplit,
               const float* __restrict__ Bm, int ldb, int transb,
               float* __restrict__ C, int ldc,
               const float* __restrict__ bias,
               const float* __restrict__ resid, int ldr,
               int K, float alpha, int flags)
{
    __shared__ uint32_t As[128][36];   // pad 36: banks 4*row+col all distinct
    __shared__ uint32_t Bs[32][136];   // pad 136: banks 8*k+n all distinct

    const int tid = threadIdx.x;
    const int warp = tid >> 5, lane = tid & 31;
    const int wm = warp >> 2, wn = warp & 3;      // 2 x 4 warp grid
    const int gid = lane >> 2, tig = lane & 3;
    const int bm = blockIdx.y * 128, bn = blockIdx.x * 128;

    float c[4][4][4];
#pragma unroll
    for (int i = 0; i < 4; i++)
#pragma unroll
        for (int j = 0; j < 4; j++)
#pragma unroll
            for (int r = 0; r < 4; r++) c[i][j][r] = 0.f;

    const int lr = tid >> 3;   // 0..31
    const int lc = tid & 7;    // 0..7

    for (int k0 = 0; k0 < K; k0 += 32) {
        // ---- A tile: 128 x 32 ----
#pragma unroll
        for (int i = 0; i < 4; i++) {
            const int row = lr + 32 * i;
            const int kg = k0 + lc * 4;
            const float* ap = (A2 != nullptr && kg >= ksplit)
                ? (A2 + (size_t)(bm + row) * lda2 + (kg - ksplit))
                : (A  + (size_t)(bm + row) * lda  + kg);
            float4 v = *(const float4*)ap;
            As[row][lc * 4 + 0] = f2tf32(v.x);
            As[row][lc * 4 + 1] = f2tf32(v.y);
            As[row][lc * 4 + 2] = f2tf32(v.z);
            As[row][lc * 4 + 3] = f2tf32(v.w);
        }
        // ---- B tile: 32 x 128 ----
        if (!transb) {
#pragma unroll
            for (int j = 0; j < 4; j++) {
                const int col = (lc + 8 * j) * 4;
                float4 v = *(const float4*)(Bm + (size_t)(k0 + lr) * ldb + bn + col);
                Bs[lr][col + 0] = f2tf32(v.x);
                Bs[lr][col + 1] = f2tf32(v.y);
                Bs[lr][col + 2] = f2tf32(v.z);
                Bs[lr][col + 3] = f2tf32(v.w);
            }
        } else {
#pragma unroll
            for (int i = 0; i < 4; i++) {
                const int n = lr + 32 * i;
                float4 v = *(const float4*)(Bm + (size_t)(bn + n) * ldb + k0 + lc * 4);
                Bs[lc * 4 + 0][n] = f2tf32(v.x);
                Bs[lc * 4 + 1][n] = f2tf32(v.y);
                Bs[lc * 4 + 2][n] = f2tf32(v.z);
                Bs[lc * 4 + 3][n] = f2tf32(v.w);
            }
        }
        __syncthreads();

#pragma unroll
        for (int ks = 0; ks < 4; ks++) {
            uint32_t a[4][4], b[4][2];
#pragma unroll
            for (int mf = 0; mf < 4; mf++) {
                const int r = wm * 64 + mf * 16 + gid;
                a[mf][0] = As[r][ks * 8 + tig];
                a[mf][1] = As[r + 8][ks * 8 + tig];
                a[mf][2] = As[r][ks * 8 + tig + 4];
                a[mf][3] = As[r + 8][ks * 8 + tig + 4];
            }
#pragma unroll
            for (int nf = 0; nf < 4; nf++) {
                const int cn = wn * 32 + nf * 8 + gid;
                b[nf][0] = Bs[ks * 8 + tig][cn];
                b[nf][1] = Bs[ks * 8 + tig + 4][cn];
            }
#pragma unroll
            for (int mf = 0; mf < 4; mf++)
#pragma unroll
                for (int nf = 0; nf < 4; nf++)
                    asm volatile(
                        "mma.sync.aligned.m16n8k8.row.col.f32.tf32.tf32.f32 "
                        "{%0,%1,%2,%3}, {%4,%5,%6,%7}, {%8,%9}, {%0,%1,%2,%3};"
                        : "+f"(c[mf][nf][0]), "+f"(c[mf][nf][1]),
                          "+f"(c[mf][nf][2]), "+f"(c[mf][nf][3])
                        : "r"(a[mf][0]), "r"(a[mf][1]), "r"(a[mf][2]), "r"(a[mf][3]),
                          "r"(b[nf][0]), "r"(b[nf][1]));
        }
        __syncthreads();
    }

    // ---- epilogue ----
#pragma unroll
    for (int mf = 0; mf < 4; mf++) {
        const int r0 = bm + wm * 64 + mf * 16 + gid;
#pragma unroll
        for (int nf = 0; nf < 4; nf++) {
            const int cn = bn + wn * 32 + nf * 8 + tig * 2;
#pragma unroll
            for (int half = 0; half < 2; half++) {
                const int row = r0 + half * 8;
                float v0 = c[mf][nf][half * 2 + 0] * alpha;
                float v1 = c[mf][nf][half * 2 + 1] * alpha;
                if (flags & FLAG_BIAS)  { v0 += bias[cn]; v1 += bias[cn + 1]; }
                if (flags & FLAG_RESID) {
                    v0 += resid[(size_t)row * ldr + cn];
                    v1 += resid[(size_t)row * ldr + cn + 1];
                }
                if (flags & FLAG_RELU)  { v0 = fmaxf(v0, 0.f); v1 = fmaxf(v1, 0.f); }
                C[(size_t)row * ldc + cn]     = v0;
                C[(size_t)row * ldc + cn + 1] = v1;
            }
        }
    }
}

// ---------------- fused attention: scores, softmax, weight-out, ctx ----------------
__global__ __launch_bounds__(256, 1)
void attention_kernel(const float* __restrict__ seq,
                      const void* __restrict__ mask,
                      const float* __restrict__ qt,   // [B,1024]
                      float* __restrict__ ctx,        // [B,1024]
                      float* __restrict__ wout)       // [B,64]
{
    extern __shared__ float s_seq[];   // 64*512
    __shared__ float s_qt[1024];
    __shared__ float s_sc[128];
    __shared__ float s_attn[128];
    __shared__ unsigned char s_mask[64];

    const int b = blockIdx.x, tid = threadIdx.x;
    const int warp = tid >> 5, lane = tid & 31;

    { // load seq tile + qt row + mask
        const float4* g = (const float4*)(seq + (size_t)b * N_ * D_);
        float4* s4 = (float4*)s_seq;
#pragma unroll 4
        for (int i = tid; i < N_ * D_ / 4; i += 256) s4[i] = g[i];
        const float4* gq = (const float4*)(qt + (size_t)b * 1024);
        ((float4*)s_qt)[tid] = gq[tid];
        if (tid < 64) {
            unsigned int mv;
            if (g_mask_word) mv = ((const unsigned int*)mask)[(size_t)b * N_ + tid];
            else             mv = ((const unsigned char*)mask)[(size_t)b * N_ + tid];
            s_mask[tid] = (mv != 0u) ? 1 : 0;
        }
    }
    __syncthreads();

    // 128 dot products (h,k), warp-per-dot
    for (int p = warp; p < 128; p += 8) {
        const int h = p >> 6, k = p & 63;
        const float* srow = s_seq + k * D_;
        const float* qrow = s_qt + h * D_;
        float acc = 0.f;
#pragma unroll
        for (int i = 0; i < 16; i++) acc += srow[lane + 32 * i] * qrow[lane + 32 * i];
#pragma unroll
        for (int o = 16; o; o >>= 1) acc += __shfl_xor_sync(0xffffffffu, acc, o);
        if (lane == 0) s_sc[p] = s_mask[k] ? -1e10f : acc;
    }
    __syncthreads();

    // softmax per head
    if (warp < 2) {
        const int h = warp;
        float v0 = s_sc[h * 64 + lane], v1 = s_sc[h * 64 + 32 + lane];
        float m = fmaxf(v0, v1);
#pragma unroll
        for (int o = 16; o; o >>= 1) m = fmaxf(m, __shfl_xor_sync(0xffffffffu, m, o));
        float e0 = __expf(v0 - m), e1 = __expf(v1 - m);
        float s = e0 + e1;
#pragma unroll
        for (int o = 16; o; o >>= 1) s += __shfl_xor_sync(0xffffffffu, s, o);
        float inv = 1.f / s;
        s_attn[h * 64 + lane]      = e0 * inv;
        s_attn[h * 64 + 32 + lane] = e1 * inv;
    }
    __syncthreads();

    if (tid < 64) wout[(size_t)b * 64 + tid] = 0.5f * (s_attn[tid] + s_attn[64 + tid]);

    // ctx[h,d] = sum_k attn[h,k] * seq[k,d]
    float acc[4] = {0.f, 0.f, 0.f, 0.f};
    for (int k = 0; k < 64; k++) {
        const float* srow = s_seq + k * D_;
        const float a0 = s_attn[k], a1 = s_attn[64 + k];
        acc[0] += a0 * srow[tid];
        acc[1] += a0 * srow[tid + 256];
        acc[2] += a1 * srow[tid];
        acc[3] += a1 * srow[tid + 256];
    }
    float* orow = ctx + (size_t)b * 1024;
    orow[tid]       = acc[0];
    orow[tid + 256] = acc[1];
    orow[tid + 512] = acc[2];
    orow[tid + 768] = acc[3];
}

// ---------------- layernorm ----------------
__global__ __launch_bounds__(128)
void ln_kernel(const float* __restrict__ x, const float* __restrict__ gam,
               const float* __restrict__ bet, float* __restrict__ y)
{
    const int b = blockIdx.x, tid = threadIdx.x;
    const float* row = x + (size_t)b * 512;
    float v[4]; float s = 0.f;
#pragma unroll
    for (int j = 0; j < 4; j++) { v[j] = row[tid + 128 * j]; s += v[j]; }
    __shared__ float red[4];
#pragma unroll
    for (int o = 16; o; o >>= 1) s += __shfl_xor_sync(0xffffffffu, s, o);
    if ((tid & 31) == 0) red[tid >> 5] = s;
    __syncthreads();
    s = red[0] + red[1] + red[2] + red[3];
    const float mu = s * (1.f / 512.f);
    float var = 0.f;
#pragma unroll
    for (int j = 0; j < 4; j++) { float d = v[j] - mu; var += d * d; }
    __syncthreads();
#pragma unroll
    for (int o = 16; o; o >>= 1) var += __shfl_xor_sync(0xffffffffu, var, o);
    if ((tid & 31) == 0) red[tid >> 5] = var;
    __syncthreads();
    var = (red[0] + red[1] + red[2] + red[3]) * (1.f / 512.f);
    const float rs = rsqrtf(var + 1e-5f);
#pragma unroll
    for (int j = 0; j < 4; j++) {
        const int c = tid + 128 * j;
        y[(size_t)b * 512 + c] = gam[c] * (v[j] - mu) * rs + bet[c];
    }
}

// ---------------- launch ----------------
extern "C" void kernel_launch(void* const* d_in, const int* in_sizes, int n_in,
                              void* d_out, int out_size)
{
    const float* src  = (const float*)d_in[0];
    const float* seq  = (const float*)d_in[1];
    const void*  mask = d_in[2];
    const float* Wq   = (const float*)d_in[3];
    const float* Wk   = (const float*)d_in[4];
    const float* Wv   = (const float*)d_in[5];
    const float* Wo   = (const float*)d_in[6];
    const float* bo   = (const float*)d_in[7];
    const float* ln_g = (const float*)d_in[8];
    const float* ln_b = (const float*)d_in[9];
    const float* W1   = (const float*)d_in[10];
    const float* b1   = (const float*)d_in[11];
    const float* W2   = (const float*)d_in[12];
    const float* b2   = (const float*)d_in[13];
    float* y    = (float*)d_out;                       // [B, 512]
    float* wout = (float*)d_out + (size_t)B_ * 512;    // [B, 64]

    float *Ck, *Cv, *QT, *CTX, *PROJ, *LN, *H1;
    cudaGetSymbolAddress((void**)&Ck,   g_Ck);
    cudaGetSymbolAddress((void**)&Cv,   g_Cv);
    cudaGetSymbolAddress((void**)&QT,   g_QT);
    cudaGetSymbolAddress((void**)&CTX,  g_CTX);
    cudaGetSymbolAddress((void**)&PROJ, g_PROJ);
    cudaGetSymbolAddress((void**)&LN,   g_LN);
    cudaGetSymbolAddress((void**)&H1,   g_H1);

    cudaFuncSetAttribute(attention_kernel,
                         cudaFuncAttributeMaxDynamicSharedMemorySize, N_ * D_ * 4);

    dim3 blk(256);

    detect_mask_kernel<<<1, 256>>>((const unsigned int*)mask);

    // Ck_h = Wq_h @ Wk_h^T / 16   (M=512, N=512 per head, trans_b)
    for (int h = 0; h < 2; h++)
        gemm_tf32<<<dim3(4, 4), blk>>>(Wq + h * 256, 512, nullptr, 0, 0,
                                       Wk + h * 256, 512, 1,
                                       Ck + h * 512, 1024,
                                       nullptr, nullptr, 0,
                                       256, 1.f / 16.f, 0);
    // Cv_h = Wv_h @ Wo[h*256 :, :]  (M=512, N=512)
    for (int h = 0; h < 2; h++)
        gemm_tf32<<<dim3(4, 4), blk>>>(Wv + h * 256, 512, nullptr, 0, 0,
                                       Wo + (size_t)h * 256 * 512, 512, 0,
                                       Cv + (size_t)h * 512 * 512, 512,
                                       nullptr, nullptr, 0,
                                       256, 1.f, 0);
    // QT = src @ Ck   (4096 x 1024, K=512)
    gemm_tf32<<<dim3(8, 32), blk>>>(src, 512, nullptr, 0, 0,
                                    Ck, 1024, 0, QT, 1024,
                                    nullptr, nullptr, 0, 512, 1.f, 0);
    // Attention
    attention_kernel<<<B_, 256, N_ * D_ * 4>>>(seq, mask, QT, CTX, wout);
    // PROJ = CTX @ Cv + bo + src   (4096 x 512, K=1024)
    gemm_tf32<<<dim3(4, 32), blk>>>(CTX, 1024, nullptr, 0, 0,
                                    Cv, 512, 0, PROJ, 512,
                                    bo, src, 512, 1024, 1.f, FLAG_BIAS | FLAG_RESID);
    // LayerNorm
    ln_kernel<<<B_, 128>>>(PROJ, ln_g, ln_b, LN);
    // H1 = relu([LN | src] @ W1 + b1)   split-A, K=1024
    gemm_tf32<<<dim3(4, 32), blk>>>(LN, 512, src, 512, 512,
                                    W1, 512, 0, H1, 512,
                                    b1, nullptr, 0, 1024, 1.f,
                                    FLAG_BIAS | FLAG_RELU);
    // y = H1 @ W2 + b2
    gemm_tf32<<<dim3(4, 32), blk>>>(H1, 512, nullptr, 0, 0,
                                    W2, 512, 0, y, 512,
                                    b2, nullptr, 0, 512, 1.f, FLAG_BIAS);
}

// round 5
// speedup vs baseline: 3.1385x; 1.4950x over previous
#include <cuda_runtime.h>
#include <cstdint>

// Shapes (fixed for this problem)
#define B_ 4096
#define N_ 64
#define D_ 512
#define H_ 2
#define DK_ 256

// ---------------- scratch (static device arrays; no allocs) ----------------
__device__ __align__(16) float g_Ck[512 * 1024];            // [D, H*D]  Wq_h @ Wk_h^T / 16
__device__ __align__(16) float g_Cv[1024 * 512];            // [H*D, D]  Wv_h @ Wo_hrows
__device__ __align__(16) float g_QT[(size_t)B_ * 1024];     // src @ Ck
__device__ __align__(16) float g_CTX[(size_t)B_ * 1024];    // attn @ seq (per head, concat)
__device__ __align__(16) float g_PROJ[(size_t)B_ * 512];
__device__ __align__(16) float g_LN[(size_t)B_ * 512];
__device__ __align__(16) float g_H1[(size_t)B_ * 512];
__device__ int g_mask_word;   // 1 = 4-byte mask elements, 0 = 1-byte

// ---------------- mask dtype detection ----------------
__global__ void detect_mask_kernel(const unsigned int* __restrict__ m)
{
    __shared__ int bad;
    if (threadIdx.x == 0) bad = 0;
    __syncthreads();
    unsigned int w = m[threadIdx.x];
    if (!(w == 0u || w == 1u || w == 0x3F800000u)) atomicOr(&bad, 1);
    __syncthreads();
    if (threadIdx.x == 0) g_mask_word = bad ? 0 : 1;
}

// ---------------- tf32 tensor-core GEMM (cp.async 2-stage pipeline) ----------------
// C[M,N] = alpha * A@B (+bias)(+resid)(relu). Tiles 128x128x32, 256 thr,
// 8 warps (2m x 4n), warp tile 64x32 via mma.m16n8k8 tf32.
// SMEM staged as raw fp32 via cp.async; RNA tf32 conversion at fragment load.
#define FLAG_BIAS  1
#define FLAG_RELU  2
#define FLAG_RESID 4

#define A_STRIDE 36     // floats per As row (pad): banks 4*gid+tig distinct
#define B_STRIDE 136    // floats per Bs row (pad): banks 8*tig+gid distinct
#define A_BUF (128 * A_STRIDE)
#define B_BUF (32 * B_STRIDE)
#define GEMM_SMEM ((2 * A_BUF + 2 * B_BUF) * 4)

__device__ __forceinline__ uint32_t f2tf32(float f)
{
    uint32_t r;
    asm("cvt.rna.tf32.f32 %0, %1;" : "=r"(r) : "f"(f));
    return r;
}
__device__ __forceinline__ void cp16(float* s, const float* g)
{
    uint32_t sa = (uint32_t)__cvta_generic_to_shared(s);
    asm volatile("cp.async.cg.shared.global [%0], [%1], 16;" :: "r"(sa), "l"(g));
}
__device__ __forceinline__ void cp4(float* s, const float* g)
{
    uint32_t sa = (uint32_t)__cvta_generic_to_shared(s);
    asm volatile("cp.async.ca.shared.global [%0], [%1], 4;" :: "r"(sa), "l"(g));
}

__device__ __forceinline__ void gemm_body(
    const float* __restrict__ A, int lda,
    const float* __restrict__ A2, int lda2, int ksplit,
    const float* __restrict__ Bm, int ldb, int transb,
    float* __restrict__ C, int ldc,
    const float* __restrict__ bias,
    const float* __restrict__ resid, int ldr,
    int K, float alpha, int flags, int bm, int bn)
{
    extern __shared__ float smem[];
    float* Asf = smem;                    // [2][128 * A_STRIDE]
    float* Bsf = smem + 2 * A_BUF;        // [2][32 * B_STRIDE]

    const int tid = threadIdx.x;
    const int warp = tid >> 5, lane = tid & 31;
    const int wm = warp >> 2, wn = warp & 3;      // 2 x 4 warp grid
    const int gid = lane >> 2, tig = lane & 3;
    const int lr = tid >> 3;   // 0..31
    const int lc = tid & 7;    // 0..7

    float c[4][4][4];
#pragma unroll
    for (int i = 0; i < 4; i++)
#pragma unroll
        for (int j = 0; j < 4; j++)
#pragma unroll
            for (int r = 0; r < 4; r++) c[i][j][r] = 0.f;

    const int KT = K >> 5;

    // stage k-tile kt into buffer buf
    auto stage = [&](int kt, int buf) {
        const int k0 = kt * 32;
        float* As = Asf + buf * A_BUF;
        float* Bs = Bsf + buf * B_BUF;
#pragma unroll
        for (int i = 0; i < 4; i++) {
            const int row = lr + 32 * i;
            const int kg = k0 + lc * 4;
            const float* ap = (A2 != nullptr && kg >= ksplit)
                ? (A2 + (size_t)(bm + row) * lda2 + (kg - ksplit))
                : (A  + (size_t)(bm + row) * lda  + kg);
            cp16(As + row * A_STRIDE + lc * 4, ap);
        }
        if (!transb) {
#pragma unroll
            for (int j = 0; j < 4; j++) {
                const int col = (lc + 8 * j) * 4;
                cp16(Bs + lr * B_STRIDE + col,
                     Bm + (size_t)(k0 + lr) * ldb + bn + col);
            }
        } else {
#pragma unroll
            for (int i = 0; i < 4; i++) {
                const int n = lr + 32 * i;
                const float* bp = Bm + (size_t)(bn + n) * ldb + k0 + lc * 4;
#pragma unroll
                for (int t = 0; t < 4; t++)
                    cp4(Bs + (lc * 4 + t) * B_STRIDE + n, bp + t);
            }
        }
        asm volatile("cp.async.commit_group;" ::: "memory");
    };

    stage(0, 0);

    for (int kt = 0; kt < KT; kt++) {
        const int buf = kt & 1;
        asm volatile("cp.async.wait_group 0;" ::: "memory");
        __syncthreads();
        if (kt + 1 < KT) stage(kt + 1, buf ^ 1);

        const float* As = Asf + buf * A_BUF;
        const float* Bs = Bsf + buf * B_BUF;
#pragma unroll
        for (int ks = 0; ks < 4; ks++) {
            uint32_t a[4][4], b[4][2];
#pragma unroll
            for (int mf = 0; mf < 4; mf++) {
                const int r = wm * 64 + mf * 16 + gid;
                a[mf][0] = f2tf32(As[r * A_STRIDE + ks * 8 + tig]);
                a[mf][1] = f2tf32(As[(r + 8) * A_STRIDE + ks * 8 + tig]);
                a[mf][2] = f2tf32(As[r * A_STRIDE + ks * 8 + tig + 4]);
                a[mf][3] = f2tf32(As[(r + 8) * A_STRIDE + ks * 8 + tig + 4]);
            }
#pragma unroll
            for (int nf = 0; nf < 4; nf++) {
                const int cn = wn * 32 + nf * 8 + gid;
                b[nf][0] = f2tf32(Bs[(ks * 8 + tig) * B_STRIDE + cn]);
                b[nf][1] = f2tf32(Bs[(ks * 8 + tig + 4) * B_STRIDE + cn]);
            }
#pragma unroll
            for (int mf = 0; mf < 4; mf++)
#pragma unroll
                for (int nf = 0; nf < 4; nf++)
                    asm volatile(
                        "mma.sync.aligned.m16n8k8.row.col.f32.tf32.tf32.f32 "
                        "{%0,%1,%2,%3}, {%4,%5,%6,%7}, {%8,%9}, {%0,%1,%2,%3};"
                        : "+f"(c[mf][nf][0]), "+f"(c[mf][nf][1]),
                          "+f"(c[mf][nf][2]), "+f"(c[mf][nf][3])
                        : "r"(a[mf][0]), "r"(a[mf][1]), "r"(a[mf][2]), "r"(a[mf][3]),
                          "r"(b[nf][0]), "r"(b[nf][1]));
        }
        __syncthreads();
    }

    // ---- epilogue ----
#pragma unroll
    for (int mf = 0; mf < 4; mf++) {
        const int r0 = bm + wm * 64 + mf * 16 + gid;
#pragma unroll
        for (int nf = 0; nf < 4; nf++) {
            const int cn = bn + wn * 32 + nf * 8 + tig * 2;
#pragma unroll
            for (int half = 0; half < 2; half++) {
                const int row = r0 + half * 8;
                float v0 = c[mf][nf][half * 2 + 0] * alpha;
                float v1 = c[mf][nf][half * 2 + 1] * alpha;
                if (flags & FLAG_BIAS)  { v0 += bias[cn]; v1 += bias[cn + 1]; }
                if (flags & FLAG_RESID) {
                    v0 += resid[(size_t)row * ldr + cn];
                    v1 += resid[(size_t)row * ldr + cn + 1];
                }
                if (flags & FLAG_RELU)  { v0 = fmaxf(v0, 0.f); v1 = fmaxf(v1, 0.f); }
                C[(size_t)row * ldc + cn]     = v0;
                C[(size_t)row * ldc + cn + 1] = v1;
            }
        }
    }
}

__global__ __launch_bounds__(256, 2)
void gemm_tf32(const float* __restrict__ A, int lda,
               const float* __restrict__ A2, int lda2, int ksplit,
               const float* __restrict__ Bm, int ldb, int transb,
               float* __restrict__ C, int ldc,
               const float* __restrict__ bias,
               const float* __restrict__ resid, int ldr,
               int K, float alpha, int flags)
{
    gemm_body(A, lda, A2, lda2, ksplit, Bm, ldb, transb, C, ldc,
              bias, resid, ldr, K, alpha, flags,
              blockIdx.y * 128, blockIdx.x * 128);
}

// ---- batched 4x (512x512x256) precompute GEMM: z selects params ----
struct GemmEntry { const float* A; const float* Bm; float* C; int ldb, transb, ldc; float alpha; };
struct GemmBatch4 { GemmEntry e[4]; };

__global__ __launch_bounds__(256, 2)
void gemm_batch4(GemmBatch4 p)
{
    const GemmEntry& e = p.e[blockIdx.z];
    gemm_body(e.A, 512, nullptr, 0, 0, e.Bm, e.ldb, e.transb, e.C, e.ldc,
              nullptr, nullptr, 0, 256, e.alpha, 0,
              blockIdx.y * 128, blockIdx.x * 128);
}

// ---------------- fused attention (512 threads): scores, softmax, weight, ctx ----
__global__ __launch_bounds__(512, 1)
void attention_kernel(const float* __restrict__ seq,
                      const void* __restrict__ mask,
                      const float* __restrict__ qt,   // [B,1024]
                      float* __restrict__ ctx,        // [B,1024]
                      float* __restrict__ wout)       // [B,64]
{
    extern __shared__ float s_seq[];   // 64*512
    __shared__ float s_qt[1024];
    __shared__ float s_sc[128];
    __shared__ float s_attn[128];
    __shared__ unsigned char s_mask[64];

    const int b = blockIdx.x, tid = threadIdx.x;
    const int warp = tid >> 5, lane = tid & 31;

    { // load seq tile + qt row + mask
        const float4* g = (const float4*)(seq + (size_t)b * N_ * D_);
        float4* s4 = (float4*)s_seq;
#pragma unroll 4
        for (int i = tid; i < N_ * D_ / 4; i += 512) s4[i] = g[i];
        if (tid < 256) {
            const float4* gq = (const float4*)(qt + (size_t)b * 1024);
            ((float4*)s_qt)[tid] = gq[tid];
        }
        if (tid < 64) {
            unsigned int mv;
            if (g_mask_word) mv = ((const unsigned int*)mask)[(size_t)b * N_ + tid];
            else             mv = ((const unsigned char*)mask)[(size_t)b * N_ + tid];
            s_mask[tid] = (mv != 0u) ? 1 : 0;
        }
    }
    __syncthreads();

    // 128 dot products (h,k), warp-per-dot, 16 warps
    for (int p = warp; p < 128; p += 16) {
        const int h = p >> 6, k = p & 63;
        const float* srow = s_seq + k * D_;
        const float* qrow = s_qt + h * D_;
        float acc = 0.f;
#pragma unroll
        for (int i = 0; i < 16; i++) acc += srow[lane + 32 * i] * qrow[lane + 32 * i];
#pragma unroll
        for (int o = 16; o; o >>= 1) acc += __shfl_xor_sync(0xffffffffu, acc, o);
        if (lane == 0) s_sc[p] = s_mask[k] ? -1e10f : acc;
    }
    __syncthreads();

    // softmax per head (warps 0,1)
    if (warp < 2) {
        const int h = warp;
        float v0 = s_sc[h * 64 + lane], v1 = s_sc[h * 64 + 32 + lane];
        float m = fmaxf(v0, v1);
#pragma unroll
        for (int o = 16; o; o >>= 1) m = fmaxf(m, __shfl_xor_sync(0xffffffffu, m, o));
        float e0 = __expf(v0 - m), e1 = __expf(v1 - m);
        float s = e0 + e1;
#pragma unroll
        for (int o = 16; o; o >>= 1) s += __shfl_xor_sync(0xffffffffu, s, o);
        float inv = 1.f / s;
        s_attn[h * 64 + lane]      = e0 * inv;
        s_attn[h * 64 + 32 + lane] = e1 * inv;
    }
    __syncthreads();

    if (tid < 64) wout[(size_t)b * 64 + tid] = 0.5f * (s_attn[tid] + s_attn[64 + tid]);

    // ctx[h,d] = sum_k attn[h,k] * seq[k,d]; thread t owns col t for both heads
    float acc0 = 0.f, acc1 = 0.f;
    for (int k = 0; k < 64; k++) {
        const float sv = s_seq[k * D_ + tid];
        acc0 += s_attn[k] * sv;
        acc1 += s_attn[64 + k] * sv;
    }
    float* orow = ctx + (size_t)b * 1024;
    orow[tid]       = acc0;
    orow[tid + 512] = acc1;
}

// ---------------- layernorm ----------------
__global__ __launch_bounds__(128)
void ln_kernel(const float* __restrict__ x, const float* __restrict__ gam,
               const float* __restrict__ bet, float* __restrict__ y)
{
    const int b = blockIdx.x, tid = threadIdx.x;
    const float* row = x + (size_t)b * 512;
    float v[4]; float s = 0.f;
#pragma unroll
    for (int j = 0; j < 4; j++) { v[j] = row[tid + 128 * j]; s += v[j]; }
    __shared__ float red[4];
#pragma unroll
    for (int o = 16; o; o >>= 1) s += __shfl_xor_sync(0xffffffffu, s, o);
    if ((tid & 31) == 0) red[tid >> 5] = s;
    __syncthreads();
    s = red[0] + red[1] + red[2] + red[3];
    const float mu = s * (1.f / 512.f);
    float var = 0.f;
#pragma unroll
    for (int j = 0; j < 4; j++) { float d = v[j] - mu; var += d * d; }
    __syncthreads();
#pragma unroll
    for (int o = 16; o; o >>= 1) var += __shfl_xor_sync(0xffffffffu, var, o);
    if ((tid & 31) == 0) red[tid >> 5] = var;
    __syncthreads();
    var = (red[0] + red[1] + red[2] + red[3]) * (1.f / 512.f);
    const float rs = rsqrtf(var + 1e-5f);
#pragma unroll
    for (int j = 0; j < 4; j++) {
        const int c = tid + 128 * j;
        y[(size_t)b * 512 + c] = gam[c] * (v[j] - mu) * rs + bet[c];
    }
}

// ---------------- launch ----------------
extern "C" void kernel_launch(void* const* d_in, const int* in_sizes, int n_in,
                              void* d_out, int out_size)
{
    const float* src  = (const float*)d_in[0];
    const float* seq  = (const float*)d_in[1];
    const void*  mask = d_in[2];
    const float* Wq   = (const float*)d_in[3];
    const float* Wk   = (const float*)d_in[4];
    const float* Wv   = (const float*)d_in[5];
    const float* Wo   = (const float*)d_in[6];
    const float* bo   = (const float*)d_in[7];
    const float* ln_g = (const float*)d_in[8];
    const float* ln_b = (const float*)d_in[9];
    const float* W1   = (const float*)d_in[10];
    const float* b1   = (const float*)d_in[11];
    const float* W2   = (const float*)d_in[12];
    const float* b2   = (const float*)d_in[13];
    float* y    = (float*)d_out;                       // [B, 512]
    float* wout = (float*)d_out + (size_t)B_ * 512;    // [B, 64]

    float *Ck, *Cv, *QT, *CTX, *PROJ, *LN, *H1;
    cudaGetSymbolAddress((void**)&Ck,   g_Ck);
    cudaGetSymbolAddress((void**)&Cv,   g_Cv);
    cudaGetSymbolAddress((void**)&QT,   g_QT);
    cudaGetSymbolAddress((void**)&CTX,  g_CTX);
    cudaGetSymbolAddress((void**)&PROJ, g_PROJ);
    cudaGetSymbolAddress((void**)&LN,   g_LN);
    cudaGetSymbolAddress((void**)&H1,   g_H1);

    cudaFuncSetAttribute(attention_kernel,
                         cudaFuncAttributeMaxDynamicSharedMemorySize, N_ * D_ * 4);
    cudaFuncSetAttribute(gemm_tf32,
                         cudaFuncAttributeMaxDynamicSharedMemorySize, GEMM_SMEM);
    cudaFuncSetAttribute(gemm_batch4,
                         cudaFuncAttributeMaxDynamicSharedMemorySize, GEMM_SMEM);

    dim3 blk(256);

    detect_mask_kernel<<<1, 256>>>((const unsigned int*)mask);

    // Batched precompute: Ck_h = Wq_h @ Wk_h^T / 16 ; Cv_h = Wv_h @ Wo[hrows,:]
    GemmBatch4 pb;
    pb.e[0] = { Wq,       Wk,                         Ck,                       512, 1, 1024, 1.f / 16.f };
    pb.e[1] = { Wq + 256, Wk + 256,                   Ck + 512,                 512, 1, 1024, 1.f / 16.f };
    pb.e[2] = { Wv,       Wo,                         Cv,                       512, 0, 512,  1.f };
    pb.e[3] = { Wv + 256, Wo + (size_t)256 * 512,     Cv + (size_t)512 * 512,   512, 0, 512,  1.f };
    gemm_batch4<<<dim3(4, 4, 4), blk, GEMM_SMEM>>>(pb);

    // QT = src @ Ck   (4096 x 1024, K=512)
    gemm_tf32<<<dim3(8, 32), blk, GEMM_SMEM>>>(src, 512, nullptr, 0, 0,
                                    Ck, 1024, 0, QT, 1024,
                                    nullptr, nullptr, 0, 512, 1.f, 0);
    // Attention
    attention_kernel<<<B_, 512, N_ * D_ * 4>>>(seq, mask, QT, CTX, wout);
    // PROJ = CTX @ Cv + bo + src   (4096 x 512, K=1024)
    gemm_tf32<<<dim3(4, 32), blk, GEMM_SMEM>>>(CTX, 1024, nullptr, 0, 0,
                                    Cv, 512, 0, PROJ, 512,
                                    bo, src, 512, 1024, 1.f, FLAG_BIAS | FLAG_RESID);
    // LayerNorm
    ln_kernel<<<B_, 128>>>(PROJ, ln_g, ln_b, LN);
    // H1 = relu([LN | src] @ W1 + b1)   split-A, K=1024
    gemm_tf32<<<dim3(4, 32), blk, GEMM_SMEM>>>(LN, 512, src, 512, 512,
                                    W1, 512, 0, H1, 512,
                                    b1, nullptr, 0, 1024, 1.f,
                                    FLAG_BIAS | FLAG_RELU);
    // y = H1 @ W2 + b2
    gemm_tf32<<<dim3(4, 32), blk, GEMM_SMEM>>>(H1, 512, nullptr, 0, 0,
                                    W2, 512, 0, y, 512,
                                    b2, nullptr, 0, 512, 1.f, FLAG_BIAS);
}

// round 6
// speedup vs baseline: 4.3345x; 1.3810x over previous
#include <cuda_runtime.h>
#include <cstdint>

// Shapes (fixed for this problem)
#define B_ 4096
#define N_ 64
#define D_ 512
#define H_ 2
#define DK_ 256

// ---------------- scratch (static device arrays; no allocs) ----------------
__device__ __align__(16) float g_Ck[512 * 1024];            // [D, H*D]  Wq_h @ Wk_h^T / 16
__device__ __align__(16) float g_Cv[1024 * 512];            // [H*D, D]  Wv_h @ Wo_hrows
__device__ __align__(16) float g_QT[(size_t)B_ * 1024];     // src @ Ck
__device__ __align__(16) float g_CTX[(size_t)B_ * 1024];    // attn @ seq (per head, concat)
__device__ __align__(16) float g_PROJ[(size_t)B_ * 512];
__device__ __align__(16) float g_LN[(size_t)B_ * 512];
__device__ __align__(16) float g_H1[(size_t)B_ * 512];
__device__ int g_mask_word;   // 1 = 4-byte mask elements, 0 = 1-byte

// ---------------- mask dtype detection ----------------
__global__ void detect_mask_kernel(const unsigned int* __restrict__ m)
{
    __shared__ int bad;
    if (threadIdx.x == 0) bad = 0;
    __syncthreads();
    unsigned int w = m[threadIdx.x];
    if (!(w == 0u || w == 1u || w == 0x3F800000u)) atomicOr(&bad, 1);
    __syncthreads();
    if (threadIdx.x == 0) g_mask_word = bad ? 0 : 1;
}

// ---------------- tf32 tensor-core GEMM (cp.async 2-stage pipeline) ----------------
#define FLAG_BIAS  1
#define FLAG_RELU  2
#define FLAG_RESID 4

#define A_STRIDE 36
#define B_STRIDE 136
#define A_BUF (128 * A_STRIDE)
#define B_BUF (32 * B_STRIDE)
#define GEMM_SMEM ((2 * A_BUF + 2 * B_BUF) * 4)

__device__ __forceinline__ uint32_t f2tf32(float f)
{
    uint32_t r;
    asm("cvt.rna.tf32.f32 %0, %1;" : "=r"(r) : "f"(f));
    return r;
}
__device__ __forceinline__ void cp16(float* s, const float* g)
{
    uint32_t sa = (uint32_t)__cvta_generic_to_shared(s);
    asm volatile("cp.async.cg.shared.global [%0], [%1], 16;" :: "r"(sa), "l"(g));
}
__device__ __forceinline__ void cp4(float* s, const float* g)
{
    uint32_t sa = (uint32_t)__cvta_generic_to_shared(s);
    asm volatile("cp.async.ca.shared.global [%0], [%1], 4;" :: "r"(sa), "l"(g));
}

__device__ __forceinline__ void gemm_body(
    const float* __restrict__ A, int lda,
    const float* __restrict__ A2, int lda2, int ksplit,
    const float* __restrict__ Bm, int ldb, int transb,
    float* __restrict__ C, int ldc,
    const float* __restrict__ bias,
    const float* __restrict__ resid, int ldr,
    int K, float alpha, int flags, int bm, int bn)
{
    extern __shared__ float smem[];
    float* Asf = smem;                    // [2][128 * A_STRIDE]
    float* Bsf = smem + 2 * A_BUF;        // [2][32 * B_STRIDE]

    const int tid = threadIdx.x;
    const int warp = tid >> 5, lane = tid & 31;
    const int wm = warp >> 2, wn = warp & 3;
    const int gid = lane >> 2, tig = lane & 3;
    const int lr = tid >> 3;
    const int lc = tid & 7;

    float c[4][4][4];
#pragma unroll
    for (int i = 0; i < 4; i++)
#pragma unroll
        for (int j = 0; j < 4; j++)
#pragma unroll
            for (int r = 0; r < 4; r++) c[i][j][r] = 0.f;

    const int KT = K >> 5;

    auto stage = [&](int kt, int buf) {
        const int k0 = kt * 32;
        float* As = Asf + buf * A_BUF;
        float* Bs = Bsf + buf * B_BUF;
#pragma unroll
        for (int i = 0; i < 4; i++) {
            const int row = lr + 32 * i;
            const int kg = k0 + lc * 4;
            const float* ap = (A2 != nullptr && kg >= ksplit)
                ? (A2 + (size_t)(bm + row) * lda2 + (kg - ksplit))
                : (A  + (size_t)(bm + row) * lda  + kg);
            cp16(As + row * A_STRIDE + lc * 4, ap);
        }
        if (!transb) {
#pragma unroll
            for (int j = 0; j < 4; j++) {
                const int col = (lc + 8 * j) * 4;
                cp16(Bs + lr * B_STRIDE + col,
                     Bm + (size_t)(k0 + lr) * ldb + bn + col);
            }
        } else {
#pragma unroll
            for (int i = 0; i < 4; i++) {
                const int n = lr + 32 * i;
                const float* bp = Bm + (size_t)(bn + n) * ldb + k0 + lc * 4;
#pragma unroll
                for (int t = 0; t < 4; t++)
                    cp4(Bs + (lc * 4 + t) * B_STRIDE + n, bp + t);
            }
        }
        asm volatile("cp.async.commit_group;" ::: "memory");
    };

    stage(0, 0);

    for (int kt = 0; kt < KT; kt++) {
        const int buf = kt & 1;
        asm volatile("cp.async.wait_group 0;" ::: "memory");
        __syncthreads();
        if (kt + 1 < KT) stage(kt + 1, buf ^ 1);

        const float* As = Asf + buf * A_BUF;
        const float* Bs = Bsf + buf * B_BUF;
#pragma unroll
        for (int ks = 0; ks < 4; ks++) {
            uint32_t a[4][4], b[4][2];
#pragma unroll
            for (int mf = 0; mf < 4; mf++) {
                const int r = wm * 64 + mf * 16 + gid;
                a[mf][0] = f2tf32(As[r * A_STRIDE + ks * 8 + tig]);
                a[mf][1] = f2tf32(As[(r + 8) * A_STRIDE + ks * 8 + tig]);
                a[mf][2] = f2tf32(As[r * A_STRIDE + ks * 8 + tig + 4]);
                a[mf][3] = f2tf32(As[(r + 8) * A_STRIDE + ks * 8 + tig + 4]);
            }
#pragma unroll
            for (int nf = 0; nf < 4; nf++) {
                const int cn = wn * 32 + nf * 8 + gid;
                b[nf][0] = f2tf32(Bs[(ks * 8 + tig) * B_STRIDE + cn]);
                b[nf][1] = f2tf32(Bs[(ks * 8 + tig + 4) * B_STRIDE + cn]);
            }
#pragma unroll
            for (int mf = 0; mf < 4; mf++)
#pragma unroll
                for (int nf = 0; nf < 4; nf++)
                    asm volatile(
                        "mma.sync.aligned.m16n8k8.row.col.f32.tf32.tf32.f32 "
                        "{%0,%1,%2,%3}, {%4,%5,%6,%7}, {%8,%9}, {%0,%1,%2,%3};"
                        : "+f"(c[mf][nf][0]), "+f"(c[mf][nf][1]),
                          "+f"(c[mf][nf][2]), "+f"(c[mf][nf][3])
                        : "r"(a[mf][0]), "r"(a[mf][1]), "r"(a[mf][2]), "r"(a[mf][3]),
                          "r"(b[nf][0]), "r"(b[nf][1]));
        }
        __syncthreads();
    }

#pragma unroll
    for (int mf = 0; mf < 4; mf++) {
        const int r0 = bm + wm * 64 + mf * 16 + gid;
#pragma unroll
        for (int nf = 0; nf < 4; nf++) {
            const int cn = bn + wn * 32 + nf * 8 + tig * 2;
#pragma unroll
            for (int half = 0; half < 2; half++) {
                const int row = r0 + half * 8;
                float v0 = c[mf][nf][half * 2 + 0] * alpha;
                float v1 = c[mf][nf][half * 2 + 1] * alpha;
                if (flags & FLAG_BIAS)  { v0 += bias[cn]; v1 += bias[cn + 1]; }
                if (flags & FLAG_RESID) {
                    v0 += resid[(size_t)row * ldr + cn];
                    v1 += resid[(size_t)row * ldr + cn + 1];
                }
                if (flags & FLAG_RELU)  { v0 = fmaxf(v0, 0.f); v1 = fmaxf(v1, 0.f); }
                C[(size_t)row * ldc + cn]     = v0;
                C[(size_t)row * ldc + cn + 1] = v1;
            }
        }
    }
}

__global__ __launch_bounds__(256, 2)
void gemm_tf32(const float* __restrict__ A, int lda,
               const float* __restrict__ A2, int lda2, int ksplit,
               const float* __restrict__ Bm, int ldb, int transb,
               float* __restrict__ C, int ldc,
               const float* __restrict__ bias,
               const float* __restrict__ resid, int ldr,
               int K, float alpha, int flags)
{
    gemm_body(A, lda, A2, lda2, ksplit, Bm, ldb, transb, C, ldc,
              bias, resid, ldr, K, alpha, flags,
              blockIdx.y * 128, blockIdx.x * 128);
}

// ---- batched 4x (512x512x256) precompute GEMM: z selects params ----
struct GemmEntry { const float* A; const float* Bm; float* C; int ldb, transb, ldc; float alpha; };
struct GemmBatch4 { GemmEntry e[4]; };

__global__ __launch_bounds__(256, 2)
void gemm_batch4(GemmBatch4 p)
{
    const GemmEntry& e = p.e[blockIdx.z];
    gemm_body(e.A, 512, nullptr, 0, 0, e.Bm, e.ldb, e.transb, e.C, e.ldc,
              nullptr, nullptr, 0, 256, e.alpha, 0,
              blockIdx.y * 128, blockIdx.x * 128);
}

// ---------------- fused attention, no-SMEM-staging (L2 reuse) ----------------
// 256 threads, tiny SMEM -> many CTAs/SM. Pass 1: stream seq from GMEM, scores
// for both heads (warp-per-k). Pass 2: re-read seq (L2-hot) for ctx.
__global__ __launch_bounds__(256)
void attention_kernel(const float* __restrict__ seq,
                      const void* __restrict__ mask,
                      const float* __restrict__ qt,   // [B,1024]
                      float* __restrict__ ctx,        // [B,1024]
                      float* __restrict__ wout)       // [B,64]
{
    __shared__ float s_qt[1024];
    __shared__ float s_sc[128];
    __shared__ float s_attn[128];
    __shared__ unsigned char s_mask[64];

    const int b = blockIdx.x, tid = threadIdx.x;
    const int warp = tid >> 5, lane = tid & 31;
    const float* sb = seq + (size_t)b * N_ * D_;

    { // qt row + mask into SMEM
        const float4* gq = (const float4*)(qt + (size_t)b * 1024);
        ((float4*)s_qt)[tid] = gq[tid];
        if (tid < 64) {
            unsigned int mv;
            if (g_mask_word) mv = ((const unsigned int*)mask)[(size_t)b * N_ + tid];
            else             mv = ((const unsigned char*)mask)[(size_t)b * N_ + tid];
            s_mask[tid] = (mv != 0u) ? 1 : 0;
        }
    }
    __syncthreads();

    // ---- pass 1: scores for both heads, warp-per-k (8 k per warp) ----
#pragma unroll
    for (int j = 0; j < 8; j++) {
        const int k = (warp << 3) | j;
        const float4* srow = (const float4*)(sb + k * D_);
        float a0 = 0.f, a1 = 0.f;
#pragma unroll
        for (int i = 0; i < 4; i++) {
            const int e = lane + 32 * i;       // float4 index, 0..127
            float4 s  = srow[e];
            float4 q0 = *(const float4*)&s_qt[e * 4];
            float4 q1 = *(const float4*)&s_qt[512 + e * 4];
            a0 += s.x * q0.x + s.y * q0.y + s.z * q0.z + s.w * q0.w;
            a1 += s.x * q1.x + s.y * q1.y + s.z * q1.z + s.w * q1.w;
        }
#pragma unroll
        for (int o = 16; o; o >>= 1) {
            a0 += __shfl_xor_sync(0xffffffffu, a0, o);
            a1 += __shfl_xor_sync(0xffffffffu, a1, o);
        }
        if (lane == 0) {
            const float neg = -1e10f;
            s_sc[k]      = s_mask[k] ? neg : a0;
            s_sc[64 + k] = s_mask[k] ? neg : a1;
        }
    }
    __syncthreads();

    // ---- softmax per head (warps 0,1) ----
    if (warp < 2) {
        const int h = warp;
        float v0 = s_sc[h * 64 + lane], v1 = s_sc[h * 64 + 32 + lane];
        float m = fmaxf(v0, v1);
#pragma unroll
        for (int o = 16; o; o >>= 1) m = fmaxf(m, __shfl_xor_sync(0xffffffffu, m, o));
        float e0 = __expf(v0 - m), e1 = __expf(v1 - m);
        float s = e0 + e1;
#pragma unroll
        for (int o = 16; o; o >>= 1) s += __shfl_xor_sync(0xffffffffu, s, o);
        float inv = 1.f / s;
        s_attn[h * 64 + lane]      = e0 * inv;
        s_attn[h * 64 + 32 + lane] = e1 * inv;
    }
    __syncthreads();

    if (tid < 64) wout[(size_t)b * 64 + tid] = 0.5f * (s_attn[tid] + s_attn[64 + tid]);

    // ---- pass 2: ctx[h,d] = sum_k attn[h,k]*seq[k,d]; thread owns 2 cols (float2) ----
    const float2* sb2 = (const float2*)sb;
    float c00 = 0.f, c01 = 0.f, c10 = 0.f, c11 = 0.f;
#pragma unroll 4
    for (int k = 0; k < 64; k++) {
        float2 v = sb2[k * 256 + tid];
        const float a0 = s_attn[k], a1 = s_attn[64 + k];
        c00 += a0 * v.x; c01 += a0 * v.y;
        c10 += a1 * v.x; c11 += a1 * v.y;
    }
    float2* orow = (float2*)(ctx + (size_t)b * 1024);
    orow[tid]       = make_float2(c00, c01);
    orow[256 + tid] = make_float2(c10, c11);
}

// ---------------- layernorm ----------------
__global__ __launch_bounds__(128)
void ln_kernel(const float* __restrict__ x, const float* __restrict__ gam,
               const float* __restrict__ bet, float* __restrict__ y)
{
    const int b = blockIdx.x, tid = threadIdx.x;
    const float* row = x + (size_t)b * 512;
    float v[4]; float s = 0.f;
#pragma unroll
    for (int j = 0; j < 4; j++) { v[j] = row[tid + 128 * j]; s += v[j]; }
    __shared__ float red[4];
#pragma unroll
    for (int o = 16; o; o >>= 1) s += __shfl_xor_sync(0xffffffffu, s, o);
    if ((tid & 31) == 0) red[tid >> 5] = s;
    __syncthreads();
    s = red[0] + red[1] + red[2] + red[3];
    const float mu = s * (1.f / 512.f);
    float var = 0.f;
#pragma unroll
    for (int j = 0; j < 4; j++) { float d = v[j] - mu; var += d * d; }
    __syncthreads();
#pragma unroll
    for (int o = 16; o; o >>= 1) var += __shfl_xor_sync(0xffffffffu, var, o);
    if ((tid & 31) == 0) red[tid >> 5] = var;
    __syncthreads();
    var = (red[0] + red[1] + red[2] + red[3]) * (1.f / 512.f);
    const float rs = rsqrtf(var + 1e-5f);
#pragma unroll
    for (int j = 0; j < 4; j++) {
        const int c = tid + 128 * j;
        y[(size_t)b * 512 + c] = gam[c] * (v[j] - mu) * rs + bet[c];
    }
}

// ---------------- launch ----------------
extern "C" void kernel_launch(void* const* d_in, const int* in_sizes, int n_in,
                              void* d_out, int out_size)
{
    const float* src  = (const float*)d_in[0];
    const float* seq  = (const float*)d_in[1];
    const void*  mask = d_in[2];
    const float* Wq   = (const float*)d_in[3];
    const float* Wk   = (const float*)d_in[4];
    const float* Wv   = (const float*)d_in[5];
    const float* Wo   = (const float*)d_in[6];
    const float* bo   = (const float*)d_in[7];
    const float* ln_g = (const float*)d_in[8];
    const float* ln_b = (const float*)d_in[9];
    const float* W1   = (const float*)d_in[10];
    const float* b1   = (const float*)d_in[11];
    const float* W2   = (const float*)d_in[12];
    const float* b2   = (const float*)d_in[13];
    float* y    = (float*)d_out;                       // [B, 512]
    float* wout = (float*)d_out + (size_t)B_ * 512;    // [B, 64]

    float *Ck, *Cv, *QT, *CTX, *PROJ, *LN, *H1;
    cudaGetSymbolAddress((void**)&Ck,   g_Ck);
    cudaGetSymbolAddress((void**)&Cv,   g_Cv);
    cudaGetSymbolAddress((void**)&QT,   g_QT);
    cudaGetSymbolAddress((void**)&CTX,  g_CTX);
    cudaGetSymbolAddress((void**)&PROJ, g_PROJ);
    cudaGetSymbolAddress((void**)&LN,   g_LN);
    cudaGetSymbolAddress((void**)&H1,   g_H1);

    cudaFuncSetAttribute(gemm_tf32,
                         cudaFuncAttributeMaxDynamicSharedMemorySize, GEMM_SMEM);
    cudaFuncSetAttribute(gemm_batch4,
                         cudaFuncAttributeMaxDynamicSharedMemorySize, GEMM_SMEM);

    dim3 blk(256);

    detect_mask_kernel<<<1, 256>>>((const unsigned int*)mask);

    // Batched precompute: Ck_h = Wq_h @ Wk_h^T / 16 ; Cv_h = Wv_h @ Wo[hrows,:]
    GemmBatch4 pb;
    pb.e[0] = { Wq,       Wk,                         Ck,                       512, 1, 1024, 1.f / 16.f };
    pb.e[1] = { Wq + 256, Wk + 256,                   Ck + 512,                 512, 1, 1024, 1.f / 16.f };
    pb.e[2] = { Wv,       Wo,                         Cv,                       512, 0, 512,  1.f };
    pb.e[3] = { Wv + 256, Wo + (size_t)256 * 512,     Cv + (size_t)512 * 512,   512, 0, 512,  1.f };
    gemm_batch4<<<dim3(4, 4, 4), blk, GEMM_SMEM>>>(pb);

    // QT = src @ Ck   (4096 x 1024, K=512)
    gemm_tf32<<<dim3(8, 32), blk, GEMM_SMEM>>>(src, 512, nullptr, 0, 0,
                                    Ck, 1024, 0, QT, 1024,
                                    nullptr, nullptr, 0, 512, 1.f, 0);
    // Attention
    attention_kernel<<<B_, 256>>>(seq, mask, QT, CTX, wout);
    // PROJ = CTX @ Cv + bo + src   (4096 x 512, K=1024)
    gemm_tf32<<<dim3(4, 32), blk, GEMM_SMEM>>>(CTX, 1024, nullptr, 0, 0,
                                    Cv, 512, 0, PROJ, 512,
                                    bo, src, 512, 1024, 1.f, FLAG_BIAS | FLAG_RESID);
    // LayerNorm
    ln_kernel<<<B_, 128>>>(PROJ, ln_g, ln_b, LN);
    // H1 = relu([LN | src] @ W1 + b1)   split-A, K=1024
    gemm_tf32<<<dim3(4, 32), blk, GEMM_SMEM>>>(LN, 512, src, 512, 512,
                                    W1, 512, 0, H1, 512,
                                    b1, nullptr, 0, 1024, 1.f,
                                    FLAG_BIAS | FLAG_RELU);
    // y = H1 @ W2 + b2
    gemm_tf32<<<dim3(4, 32), blk, GEMM_SMEM>>>(H1, 512, nullptr, 0, 0,
                                    W2, 512, 0, y, 512,
                                    b2, nullptr, 0, 512, 1.f, FLAG_BIAS);
}

// round 7
// speedup vs baseline: 4.6898x; 1.0820x over previous
#include <cuda_runtime.h>
#include <cstdint>

// Shapes (fixed for this problem)
#define B_ 4096
#define N_ 64
#define D_ 512
#define H_ 2
#define DK_ 256

// ---------------- scratch (static device arrays; no allocs) ----------------
__device__ __align__(16) float g_Ck[512 * 1024];            // [D, H*D]  Wq_h @ Wk_h^T / 16
__device__ __align__(16) float g_Cv[1024 * 512];            // [H*D, D]  Wv_h @ Wo_hrows
__device__ __align__(16) float g_QT[(size_t)B_ * 1024];     // src @ Ck
__device__ __align__(16) float g_CTX[(size_t)B_ * 1024];    // attn @ seq (per head, concat)
__device__ __align__(16) float g_PROJ[(size_t)B_ * 512];
__device__ __align__(16) float g_LN[(size_t)B_ * 512];
__device__ __align__(16) float g_H1[(size_t)B_ * 512];
__device__ int g_mask_word;   // 1 = 4-byte mask elements, 0 = 1-byte

// ---------------- mask dtype detection ----------------
__global__ void detect_mask_kernel(const unsigned int* __restrict__ m)
{
    __shared__ int bad;
    if (threadIdx.x == 0) bad = 0;
    __syncthreads();
    unsigned int w = m[threadIdx.x];
    if (!(w == 0u || w == 1u || w == 0x3F800000u)) atomicOr(&bad, 1);
    __syncthreads();
    if (threadIdx.x == 0) g_mask_word = bad ? 0 : 1;
}

// ---------------- tf32 tensor-core GEMM (cp.async 2-stage pipeline) ----------------
#define FLAG_BIAS  1
#define FLAG_RELU  2
#define FLAG_RESID 4

#define A_STRIDE 36
#define B_STRIDE 136
#define B_BUF (32 * B_STRIDE)
// MF=4: 128-row tiles; MF=2: 64-row tiles
#define GEMM_SMEM_MF(MF) ((2 * (MF) * 32 * A_STRIDE + 2 * B_BUF) * 4)

__device__ __forceinline__ uint32_t f2tf32(float f)
{
    uint32_t r;
    asm("cvt.rna.tf32.f32 %0, %1;" : "=r"(r) : "f"(f));
    return r;
}
__device__ __forceinline__ void cp16(float* s, const float* g)
{
    uint32_t sa = (uint32_t)__cvta_generic_to_shared(s);
    asm volatile("cp.async.cg.shared.global [%0], [%1], 16;" :: "r"(sa), "l"(g));
}
__device__ __forceinline__ void cp4(float* s, const float* g)
{
    uint32_t sa = (uint32_t)__cvta_generic_to_shared(s);
    asm volatile("cp.async.ca.shared.global [%0], [%1], 4;" :: "r"(sa), "l"(g));
}

template<int MF>   // CTA rows = MF*32, warp rows = MF*16
__device__ __forceinline__ void gemm_body(
    const float* __restrict__ A, int lda,
    const float* __restrict__ A2, int lda2, int ksplit,
    const float* __restrict__ Bm, int ldb, int transb,
    float* __restrict__ C, int ldc,
    const float* __restrict__ bias,
    const float* __restrict__ resid, int ldr,
    int K, float alpha, int flags, int bm, int bn)
{
    constexpr int ABUF = MF * 32 * A_STRIDE;
    extern __shared__ float smem[];
    float* Asf = smem;                    // [2][MF*32 * A_STRIDE]
    float* Bsf = smem + 2 * ABUF;         // [2][32 * B_STRIDE]

    const int tid = threadIdx.x;
    const int warp = tid >> 5, lane = tid & 31;
    const int wm = warp >> 2, wn = warp & 3;
    const int gid = lane >> 2, tig = lane & 3;
    const int lr = tid >> 3;
    const int lc = tid & 7;

    float c[MF][4][4];
#pragma unroll
    for (int i = 0; i < MF; i++)
#pragma unroll
        for (int j = 0; j < 4; j++)
#pragma unroll
            for (int r = 0; r < 4; r++) c[i][j][r] = 0.f;

    const int KT = K >> 5;

    auto stage = [&](int kt, int buf) {
        const int k0 = kt * 32;
        float* As = Asf + buf * ABUF;
        float* Bs = Bsf + buf * B_BUF;
#pragma unroll
        for (int i = 0; i < MF; i++) {
            const int row = lr + 32 * i;
            const int kg = k0 + lc * 4;
            const float* ap = (A2 != nullptr && kg >= ksplit)
                ? (A2 + (size_t)(bm + row) * lda2 + (kg - ksplit))
                : (A  + (size_t)(bm + row) * lda  + kg);
            cp16(As + row * A_STRIDE + lc * 4, ap);
        }
        if (!transb) {
#pragma unroll
            for (int j = 0; j < 4; j++) {
                const int col = (lc + 8 * j) * 4;
                cp16(Bs + lr * B_STRIDE + col,
                     Bm + (size_t)(k0 + lr) * ldb + bn + col);
            }
        } else {
#pragma unroll
            for (int i = 0; i < 4; i++) {
                const int n = lr + 32 * i;
                const float* bp = Bm + (size_t)(bn + n) * ldb + k0 + lc * 4;
#pragma unroll
                for (int t = 0; t < 4; t++)
                    cp4(Bs + (lc * 4 + t) * B_STRIDE + n, bp + t);
            }
        }
        asm volatile("cp.async.commit_group;" ::: "memory");
    };

    stage(0, 0);

    for (int kt = 0; kt < KT; kt++) {
        const int buf = kt & 1;
        asm volatile("cp.async.wait_group 0;" ::: "memory");
        __syncthreads();
        if (kt + 1 < KT) stage(kt + 1, buf ^ 1);

        const float* As = Asf + buf * ABUF;
        const float* Bs = Bsf + buf * B_BUF;
#pragma unroll
        for (int ks = 0; ks < 4; ks++) {
            uint32_t a[MF][4], b[4][2];
#pragma unroll
            for (int mf = 0; mf < MF; mf++) {
                const int r = wm * (MF * 16) + mf * 16 + gid;
                a[mf][0] = f2tf32(As[r * A_STRIDE + ks * 8 + tig]);
                a[mf][1] = f2tf32(As[(r + 8) * A_STRIDE + ks * 8 + tig]);
                a[mf][2] = f2tf32(As[r * A_STRIDE + ks * 8 + tig + 4]);
                a[mf][3] = f2tf32(As[(r + 8) * A_STRIDE + ks * 8 + tig + 4]);
            }
#pragma unroll
            for (int nf = 0; nf < 4; nf++) {
                const int cn = wn * 32 + nf * 8 + gid;
                b[nf][0] = f2tf32(Bs[(ks * 8 + tig) * B_STRIDE + cn]);
                b[nf][1] = f2tf32(Bs[(ks * 8 + tig + 4) * B_STRIDE + cn]);
            }
#pragma unroll
            for (int mf = 0; mf < MF; mf++)
#pragma unroll
                for (int nf = 0; nf < 4; nf++)
                    asm volatile(
                        "mma.sync.aligned.m16n8k8.row.col.f32.tf32.tf32.f32 "
                        "{%0,%1,%2,%3}, {%4,%5,%6,%7}, {%8,%9}, {%0,%1,%2,%3};"
                        : "+f"(c[mf][nf][0]), "+f"(c[mf][nf][1]),
                          "+f"(c[mf][nf][2]), "+f"(c[mf][nf][3])
                        : "r"(a[mf][0]), "r"(a[mf][1]), "r"(a[mf][2]), "r"(a[mf][3]),
                          "r"(b[nf][0]), "r"(b[nf][1]));
        }
        __syncthreads();
    }

#pragma unroll
    for (int mf = 0; mf < MF; mf++) {
        const int r0 = bm + wm * (MF * 16) + mf * 16 + gid;
#pragma unroll
        for (int nf = 0; nf < 4; nf++) {
            const int cn = bn + wn * 32 + nf * 8 + tig * 2;
#pragma unroll
            for (int half = 0; half < 2; half++) {
                const int row = r0 + half * 8;
                float v0 = c[mf][nf][half * 2 + 0] * alpha;
                float v1 = c[mf][nf][half * 2 + 1] * alpha;
                if (flags & FLAG_BIAS)  { v0 += bias[cn]; v1 += bias[cn + 1]; }
                if (flags & FLAG_RESID) {
                    v0 += resid[(size_t)row * ldr + cn];
                    v1 += resid[(size_t)row * ldr + cn + 1];
                }
                if (flags & FLAG_RELU)  { v0 = fmaxf(v0, 0.f); v1 = fmaxf(v1, 0.f); }
                C[(size_t)row * ldc + cn]     = v0;
                C[(size_t)row * ldc + cn + 1] = v1;
            }
        }
    }
}

__global__ __launch_bounds__(256, 2)
void gemm_tf32_m128(const float* __restrict__ A, int lda,
               const float* __restrict__ A2, int lda2, int ksplit,
               const float* __restrict__ Bm, int ldb, int transb,
               float* __restrict__ C, int ldc,
               const float* __restrict__ bias,
               const float* __restrict__ resid, int ldr,
               int K, float alpha, int flags)
{
    gemm_body<4>(A, lda, A2, lda2, ksplit, Bm, ldb, transb, C, ldc,
                 bias, resid, ldr, K, alpha, flags,
                 blockIdx.y * 128, blockIdx.x * 128);
}

__global__ __launch_bounds__(256)
void gemm_tf32_m64(const float* __restrict__ A, int lda,
               const float* __restrict__ A2, int lda2, int ksplit,
               const float* __restrict__ Bm, int ldb, int transb,
               float* __restrict__ C, int ldc,
               const float* __restrict__ bias,
               const float* __restrict__ resid, int ldr,
               int K, float alpha, int flags)
{
    gemm_body<2>(A, lda, A2, lda2, ksplit, Bm, ldb, transb, C, ldc,
                 bias, resid, ldr, K, alpha, flags,
                 blockIdx.y * 64, blockIdx.x * 128);
}

// ---- batched 4x (512x512x256) precompute GEMM: z selects params ----
struct GemmEntry { const float* A; const float* Bm; float* C; int ldb, transb, ldc; float alpha; };
struct GemmBatch4 { GemmEntry e[4]; };

__global__ __launch_bounds__(256, 2)
void gemm_batch4(GemmBatch4 p)
{
    const GemmEntry& e = p.e[blockIdx.z];
    gemm_body<4>(e.A, 512, nullptr, 0, 0, e.Bm, e.ldb, e.transb, e.C, e.ldc,
                 nullptr, nullptr, 0, 256, e.alpha, 0,
                 blockIdx.y * 128, blockIdx.x * 128);
}

// ---------------- flash attention: single pass over seq, online softmax ----
// 256 threads/CTA, one CTA per batch row. 4 chunks of 16 rows, cp.async
// double-buffered (2 x 32KB). seq read exactly once from DRAM.
#define CHUNK 16
#define CHUNK_FLOATS (CHUNK * D_)          // 8192
#define ATTN_SMEM (2 * CHUNK_FLOATS * 4)   // 64 KB

__global__ __launch_bounds__(256)
void attention_kernel(const float* __restrict__ seq,
                      const void* __restrict__ mask,
                      const float* __restrict__ qt,   // [B,1024]
                      float* __restrict__ ctx,        // [B,1024]
                      float* __restrict__ wout)       // [B,64]
{
    extern __shared__ float s_buf[];       // [2][CHUNK_FLOATS]
    __shared__ float s_all[128];           // raw scores, both heads
    __shared__ float s_m[2], s_l[2], s_f[2], s_e[2][CHUNK];
    __shared__ unsigned char s_mask[64];

    const int b = blockIdx.x, tid = threadIdx.x;
    const int warp = tid >> 5, lane = tid & 31;
    const float* sb = seq + (size_t)b * N_ * D_;

    // q fragments in registers (lane-strided float4, reused across all chunks)
    float4 q0f[4], q1f[4];
    {
        const float4* q0p = (const float4*)(qt + (size_t)b * 1024);
        const float4* q1p = q0p + 128;
#pragma unroll
        for (int i = 0; i < 4; i++) {
            q0f[i] = q0p[lane + 32 * i];
            q1f[i] = q1p[lane + 32 * i];
        }
    }
    if (tid < 64) {
        unsigned int mv;
        if (g_mask_word) mv = ((const unsigned int*)mask)[(size_t)b * N_ + tid];
        else             mv = ((const unsigned char*)mask)[(size_t)b * N_ + tid];
        s_mask[tid] = (mv != 0u) ? 1 : 0;
    }
    if (tid < 2) { s_m[tid] = -3e38f; s_l[tid] = 0.f; }

    auto stage = [&](int c, int buf) {
        float* dst = s_buf + buf * CHUNK_FLOATS;
        const float* src = sb + c * CHUNK_FLOATS;
#pragma unroll
        for (int i = 0; i < 8; i++) {
            const int e = (tid + 256 * i) * 4;
            cp16(dst + e, src + e);
        }
        asm volatile("cp.async.commit_group;" ::: "memory");
    };

    stage(0, 0);
    __syncthreads();   // s_mask / s_m init visible

    float a00 = 0.f, a01 = 0.f, a10 = 0.f, a11 = 0.f;

    for (int c = 0; c < 4; c++) {
        const int buf = c & 1;
        asm volatile("cp.async.wait_group 0;" ::: "memory");
        __syncthreads();
        if (c < 3) stage(c + 1, buf ^ 1);

        const float* rows = s_buf + buf * CHUNK_FLOATS;

        // scores: warp w handles chunk rows 2w, 2w+1 (both heads)
#pragma unroll
        for (int rr = 0; rr < 2; rr++) {
            const int k = 2 * warp + rr;
            const float4* r4 = (const float4*)(rows + k * D_);
            float a0 = 0.f, a1 = 0.f;
#pragma unroll
            for (int i = 0; i < 4; i++) {
                float4 s = r4[lane + 32 * i];
                a0 += s.x * q0f[i].x + s.y * q0f[i].y + s.z * q0f[i].z + s.w * q0f[i].w;
                a1 += s.x * q1f[i].x + s.y * q1f[i].y + s.z * q1f[i].z + s.w * q1f[i].w;
            }
#pragma unroll
            for (int o = 16; o; o >>= 1) {
                a0 += __shfl_xor_sync(0xffffffffu, a0, o);
                a1 += __shfl_xor_sync(0xffffffffu, a1, o);
            }
            if (lane == 0) {
                const int kg = c * CHUNK + k;
                const bool mk = s_mask[kg] != 0;
                s_all[kg]      = mk ? -1e10f : a0;
                s_all[64 + kg] = mk ? -1e10f : a1;
            }
        }
        __syncthreads();

        // online softmax update (warp 0 -> head 0, warp 1 -> head 1)
        if (warp < 2) {
            const int h = warp;
            float s = (lane < CHUNK) ? s_all[h * 64 + c * CHUNK + lane] : -3e38f;
            float cm = s;
#pragma unroll
            for (int o = 16; o; o >>= 1) cm = fmaxf(cm, __shfl_xor_sync(0xffffffffu, cm, o));
            const float m_old = s_m[h];
            const float m_new = fmaxf(m_old, cm);
            float e = (lane < CHUNK) ? __expf(s - m_new) : 0.f;
            float se = e;
#pragma unroll
            for (int o = 16; o; o >>= 1) se += __shfl_xor_sync(0xffffffffu, se, o);
            if (lane < CHUNK) s_e[h][lane] = e;
            if (lane == 0) {
                const float f = __expf(m_old - m_new);
                s_f[h] = f; s_m[h] = m_new;
                s_l[h] = s_l[h] * f + se;
            }
        }
        __syncthreads();

        // accumulate: thread owns cols (2*tid, 2*tid+1)
        const float f0 = s_f[0], f1 = s_f[1];
        a00 *= f0; a01 *= f0; a10 *= f1; a11 *= f1;
        const float2* rows2 = (const float2*)rows;
#pragma unroll
        for (int k = 0; k < CHUNK; k++) {
            float2 v = rows2[k * 256 + tid];
            const float e0 = s_e[0][k], e1 = s_e[1][k];
            a00 += e0 * v.x; a01 += e0 * v.y;
            a10 += e1 * v.x; a11 += e1 * v.y;
        }
        __syncthreads();   // buffer consumed before next overwrite
    }

    const float inv0 = 1.f / s_l[0], inv1 = 1.f / s_l[1];
    float2* orow = (float2*)(ctx + (size_t)b * 1024);
    orow[tid]       = make_float2(a00 * inv0, a01 * inv0);
    orow[256 + tid] = make_float2(a10 * inv1, a11 * inv1);

    if (tid < 64) {
        const float m0 = s_m[0], m1 = s_m[1];
        const float at0 = __expf(s_all[tid]      - m0) * inv0;
        const float at1 = __expf(s_all[64 + tid] - m1) * inv1;
        wout[(size_t)b * 64 + tid] = 0.5f * (at0 + at1);
    }
}

// ---------------- layernorm ----------------
__global__ __launch_bounds__(128)
void ln_kernel(const float* __restrict__ x, const float* __restrict__ gam,
               const float* __restrict__ bet, float* __restrict__ y)
{
    const int b = blockIdx.x, tid = threadIdx.x;
    const float* row = x + (size_t)b * 512;
    float v[4]; float s = 0.f;
#pragma unroll
    for (int j = 0; j < 4; j++) { v[j] = row[tid + 128 * j]; s += v[j]; }
    __shared__ float red[4];
#pragma unroll
    for (int o = 16; o; o >>= 1) s += __shfl_xor_sync(0xffffffffu, s, o);
    if ((tid & 31) == 0) red[tid >> 5] = s;
    __syncthreads();
    s = red[0] + red[1] + red[2] + red[3];
    const float mu = s * (1.f / 512.f);
    float var = 0.f;
#pragma unroll
    for (int j = 0; j < 4; j++) { float d = v[j] - mu; var += d * d; }
    __syncthreads();
#pragma unroll
    for (int o = 16; o; o >>= 1) var += __shfl_xor_sync(0xffffffffu, var, o);
    if ((tid & 31) == 0) red[tid >> 5] = var;
    __syncthreads();
    var = (red[0] + red[1] + red[2] + red[3]) * (1.f / 512.f);
    const float rs = rsqrtf(var + 1e-5f);
#pragma unroll
    for (int j = 0; j < 4; j++) {
        const int c = tid + 128 * j;
        y[(size_t)b * 512 + c] = gam[c] * (v[j] - mu) * rs + bet[c];
    }
}

// ---------------- launch ----------------
extern "C" void kernel_launch(void* const* d_in, const int* in_sizes, int n_in,
                              void* d_out, int out_size)
{
    const float* src  = (const float*)d_in[0];
    const float* seq  = (const float*)d_in[1];
    const void*  mask = d_in[2];
    const float* Wq   = (const float*)d_in[3];
    const float* Wk   = (const float*)d_in[4];
    const float* Wv   = (const float*)d_in[5];
    const float* Wo   = (const float*)d_in[6];
    const float* bo   = (const float*)d_in[7];
    const float* ln_g = (const float*)d_in[8];
    const float* ln_b = (const float*)d_in[9];
    const float* W1   = (const float*)d_in[10];
    const float* b1   = (const float*)d_in[11];
    const float* W2   = (const float*)d_in[12];
    const float* b2   = (const float*)d_in[13];
    float* y    = (float*)d_out;                       // [B, 512]
    float* wout = (float*)d_out + (size_t)B_ * 512;    // [B, 64]

    float *Ck, *Cv, *QT, *CTX, *PROJ, *LN, *H1;
    cudaGetSymbolAddress((void**)&Ck,   g_Ck);
    cudaGetSymbolAddress((void**)&Cv,   g_Cv);
    cudaGetSymbolAddress((void**)&QT,   g_QT);
    cudaGetSymbolAddress((void**)&CTX,  g_CTX);
    cudaGetSymbolAddress((void**)&PROJ, g_PROJ);
    cudaGetSymbolAddress((void**)&LN,   g_LN);
    cudaGetSymbolAddress((void**)&H1,   g_H1);

    cudaFuncSetAttribute(gemm_tf32_m128,
                         cudaFuncAttributeMaxDynamicSharedMemorySize, GEMM_SMEM_MF(4));
    cudaFuncSetAttribute(gemm_tf32_m64,
                         cudaFuncAttributeMaxDynamicSharedMemorySize, GEMM_SMEM_MF(2));
    cudaFuncSetAttribute(gemm_batch4,
                         cudaFuncAttributeMaxDynamicSharedMemorySize, GEMM_SMEM_MF(4));
    cudaFuncSetAttribute(attention_kernel,
                         cudaFuncAttributeMaxDynamicSharedMemorySize, ATTN_SMEM);

    dim3 blk(256);

    detect_mask_kernel<<<1, 256>>>((const unsigned int*)mask);

    // Batched precompute: Ck_h = Wq_h @ Wk_h^T / 16 ; Cv_h = Wv_h @ Wo[hrows,:]
    GemmBatch4 pb;
    pb.e[0] = { Wq,       Wk,                         Ck,                       512, 1, 1024, 1.f / 16.f };
    pb.e[1] = { Wq + 256, Wk + 256,                   Ck + 512,                 512, 1, 1024, 1.f / 16.f };
    pb.e[2] = { Wv,       Wo,                         Cv,                       512, 0, 512,  1.f };
    pb.e[3] = { Wv + 256, Wo + (size_t)256 * 512,     Cv + (size_t)512 * 512,   512, 0, 512,  1.f };
    gemm_batch4<<<dim3(4, 4, 4), blk, GEMM_SMEM_MF(4)>>>(pb);

    // QT = src @ Ck   (4096 x 1024, K=512), 128-row tiles (256 CTAs)
    gemm_tf32_m128<<<dim3(8, 32), blk, GEMM_SMEM_MF(4)>>>(src, 512, nullptr, 0, 0,
                                    Ck, 1024, 0, QT, 1024,
                                    nullptr, nullptr, 0, 512, 1.f, 0);
    // Flash attention (single pass over seq)
    attention_kernel<<<B_, 256, ATTN_SMEM>>>(seq, mask, QT, CTX, wout);
    // PROJ = CTX @ Cv + bo + src   (4096 x 512, K=1024), 64-row tiles (256 CTAs)
    gemm_tf32_m64<<<dim3(4, 64), blk, GEMM_SMEM_MF(2)>>>(CTX, 1024, nullptr, 0, 0,
                                    Cv, 512, 0, PROJ, 512,
                                    bo, src, 512, 1024, 1.f, FLAG_BIAS | FLAG_RESID);
    // LayerNorm
    ln_kernel<<<B_, 128>>>(PROJ, ln_g, ln_b, LN);
    // H1 = relu([LN | src] @ W1 + b1)   split-A, K=1024
    gemm_tf32_m64<<<dim3(4, 64), blk, GEMM_SMEM_MF(2)>>>(LN, 512, src, 512, 512,
                                    W1, 512, 0, H1, 512,
                                    b1, nullptr, 0, 1024, 1.f,
                                    FLAG_BIAS | FLAG_RELU);
    // y = H1 @ W2 + b2
    gemm_tf32_m64<<<dim3(4, 64), blk, GEMM_SMEM_MF(2)>>>(H1, 512, nullptr, 0, 0,
                                    W2, 512, 0, y, 512,
                                    b2, nullptr, 0, 512, 1.f, FLAG_BIAS);
}

// round 8
// speedup vs baseline: 4.6903x; 1.0001x over previous
#include <cuda_runtime.h>
#include <cstdint>

// Shapes (fixed for this problem)
#define B_ 4096
#define N_ 64
#define D_ 512
#define H_ 2
#define DK_ 256

// ---------------- scratch (static device arrays; no allocs) ----------------
__device__ __align__(16) float g_Ck[512 * 1024];            // [D, H*D]  Wq_h @ Wk_h^T / 16
__device__ __align__(16) float g_Cv[1024 * 512];            // [H*D, D]  Wv_h @ Wo_hrows
__device__ __align__(16) float g_QT[(size_t)B_ * 1024];     // src @ Ck
__device__ __align__(16) float g_CTX[(size_t)B_ * 1024];    // attn @ seq (per head, concat)
__device__ __align__(16) float g_PROJ[(size_t)B_ * 512];
__device__ __align__(16) float g_LN[(size_t)B_ * 512];
__device__ __align__(16) float g_H1[(size_t)B_ * 512];
__device__ int g_mask_word;   // 1 = 4-byte mask elements, 0 = 1-byte

// ---------------- mask dtype detection ----------------
__global__ void detect_mask_kernel(const unsigned int* __restrict__ m)
{
    __shared__ int bad;
    if (threadIdx.x == 0) bad = 0;
    __syncthreads();
    unsigned int w = m[threadIdx.x];
    if (!(w == 0u || w == 1u || w == 0x3F800000u)) atomicOr(&bad, 1);
    __syncthreads();
    if (threadIdx.x == 0) g_mask_word = bad ? 0 : 1;
}

// ---------------- tf32 tensor-core GEMM (cp.async 3-stage pipeline) ----------------
#define FLAG_BIAS  1
#define FLAG_RELU  2
#define FLAG_RESID 4

#define A_STRIDE 36
#define B_STRIDE 136
#define B_BUF (32 * B_STRIDE)
// 3 pipeline stages. MF=4: 128-row tiles; MF=2: 64-row tiles
#define GEMM_SMEM_MF(MF) (3 * ((MF) * 32 * A_STRIDE + B_BUF) * 4)

__device__ __forceinline__ uint32_t f2tf32(float f)
{
    uint32_t r;
    asm("cvt.rna.tf32.f32 %0, %1;" : "=r"(r) : "f"(f));
    return r;
}
__device__ __forceinline__ void cp16(float* s, const float* g)
{
    uint32_t sa = (uint32_t)__cvta_generic_to_shared(s);
    asm volatile("cp.async.cg.shared.global [%0], [%1], 16;" :: "r"(sa), "l"(g));
}
__device__ __forceinline__ void cp4(float* s, const float* g)
{
    uint32_t sa = (uint32_t)__cvta_generic_to_shared(s);
    asm volatile("cp.async.ca.shared.global [%0], [%1], 4;" :: "r"(sa), "l"(g));
}

template<int MF>   // CTA rows = MF*32, warp rows = MF*16
__device__ __forceinline__ void gemm_body(
    const float* __restrict__ A, int lda,
    const float* __restrict__ A2, int lda2, int ksplit,
    const float* __restrict__ Bm, int ldb, int transb,
    float* __restrict__ C, int ldc,
    const float* __restrict__ bias,
    const float* __restrict__ resid, int ldr,
    int K, float alpha, int flags, int bm, int bn)
{
    constexpr int ABUF = MF * 32 * A_STRIDE;
    extern __shared__ float smem[];
    float* Asf = smem;                    // [3][MF*32 * A_STRIDE]
    float* Bsf = smem + 3 * ABUF;         // [3][32 * B_STRIDE]

    const int tid = threadIdx.x;
    const int warp = tid >> 5, lane = tid & 31;
    const int wm = warp >> 2, wn = warp & 3;
    const int gid = lane >> 2, tig = lane & 3;
    const int lr = tid >> 3;
    const int lc = tid & 7;

    float c[MF][4][4];
#pragma unroll
    for (int i = 0; i < MF; i++)
#pragma unroll
        for (int j = 0; j < 4; j++)
#pragma unroll
            for (int r = 0; r < 4; r++) c[i][j][r] = 0.f;

    const int KT = K >> 5;

    auto stage = [&](int kt, int slot) {
        const int k0 = kt * 32;
        float* As = Asf + slot * ABUF;
        float* Bs = Bsf + slot * B_BUF;
#pragma unroll
        for (int i = 0; i < MF; i++) {
            const int row = lr + 32 * i;
            const int kg = k0 + lc * 4;
            const float* ap = (A2 != nullptr && kg >= ksplit)
                ? (A2 + (size_t)(bm + row) * lda2 + (kg - ksplit))
                : (A  + (size_t)(bm + row) * lda  + kg);
            cp16(As + row * A_STRIDE + lc * 4, ap);
        }
        if (!transb) {
#pragma unroll
            for (int j = 0; j < 4; j++) {
                const int col = (lc + 8 * j) * 4;
                cp16(Bs + lr * B_STRIDE + col,
                     Bm + (size_t)(k0 + lr) * ldb + bn + col);
            }
        } else {
#pragma unroll
            for (int i = 0; i < 4; i++) {
                const int n = lr + 32 * i;
                const float* bp = Bm + (size_t)(bn + n) * ldb + k0 + lc * 4;
#pragma unroll
                for (int t = 0; t < 4; t++)
                    cp4(Bs + (lc * 4 + t) * B_STRIDE + n, bp + t);
            }
        }
        asm volatile("cp.async.commit_group;" ::: "memory");
    };

    stage(0, 0);
    if (KT > 1) stage(1, 1);

    int slot = 0;
    for (int kt = 0; kt < KT; kt++) {
        asm volatile("cp.async.wait_group 1;" ::: "memory");
        __syncthreads();
        // stage kt+2 into the slot retired at the sync above
        if (kt + 2 < KT) {
            int ns = slot + 2; if (ns >= 3) ns -= 3;
            stage(kt + 2, ns);
        }

        const float* As = Asf + slot * ABUF;
        const float* Bs = Bsf + slot * B_BUF;
#pragma unroll
        for (int ks = 0; ks < 4; ks++) {
            uint32_t a[MF][4], b[4][2];
#pragma unroll
            for (int mf = 0; mf < MF; mf++) {
                const int r = wm * (MF * 16) + mf * 16 + gid;
                a[mf][0] = f2tf32(As[r * A_STRIDE + ks * 8 + tig]);
                a[mf][1] = f2tf32(As[(r + 8) * A_STRIDE + ks * 8 + tig]);
                a[mf][2] = f2tf32(As[r * A_STRIDE + ks * 8 + tig + 4]);
                a[mf][3] = f2tf32(As[(r + 8) * A_STRIDE + ks * 8 + tig + 4]);
            }
#pragma unroll
            for (int nf = 0; nf < 4; nf++) {
                const int cn = wn * 32 + nf * 8 + gid;
                b[nf][0] = f2tf32(Bs[(ks * 8 + tig) * B_STRIDE + cn]);
                b[nf][1] = f2tf32(Bs[(ks * 8 + tig + 4) * B_STRIDE + cn]);
            }
#pragma unroll
            for (int mf = 0; mf < MF; mf++)
#pragma unroll
                for (int nf = 0; nf < 4; nf++)
                    asm volatile(
                        "mma.sync.aligned.m16n8k8.row.col.f32.tf32.tf32.f32 "
                        "{%0,%1,%2,%3}, {%4,%5,%6,%7}, {%8,%9}, {%0,%1,%2,%3};"
                        : "+f"(c[mf][nf][0]), "+f"(c[mf][nf][1]),
                          "+f"(c[mf][nf][2]), "+f"(c[mf][nf][3])
                        : "r"(a[mf][0]), "r"(a[mf][1]), "r"(a[mf][2]), "r"(a[mf][3]),
                          "r"(b[nf][0]), "r"(b[nf][1]));
        }
        slot++; if (slot == 3) slot = 0;
    }

#pragma unroll
    for (int mf = 0; mf < MF; mf++) {
        const int r0 = bm + wm * (MF * 16) + mf * 16 + gid;
#pragma unroll
        for (int nf = 0; nf < 4; nf++) {
            const int cn = bn + wn * 32 + nf * 8 + tig * 2;
#pragma unroll
            for (int half = 0; half < 2; half++) {
                const int row = r0 + half * 8;
                float v0 = c[mf][nf][half * 2 + 0] * alpha;
                float v1 = c[mf][nf][half * 2 + 1] * alpha;
                if (flags & FLAG_BIAS)  { v0 += bias[cn]; v1 += bias[cn + 1]; }
                if (flags & FLAG_RESID) {
                    v0 += resid[(size_t)row * ldr + cn];
                    v1 += resid[(size_t)row * ldr + cn + 1];
                }
                if (flags & FLAG_RELU)  { v0 = fmaxf(v0, 0.f); v1 = fmaxf(v1, 0.f); }
                C[(size_t)row * ldc + cn]     = v0;
                C[(size_t)row * ldc + cn + 1] = v1;
            }
        }
    }
}

__global__ __launch_bounds__(256, 2)
void gemm_tf32_m128(const float* __restrict__ A, int lda,
               const float* __restrict__ A2, int lda2, int ksplit,
               const float* __restrict__ Bm, int ldb, int transb,
               float* __restrict__ C, int ldc,
               const float* __restrict__ bias,
               const float* __restrict__ resid, int ldr,
               int K, float alpha, int flags)
{
    gemm_body<4>(A, lda, A2, lda2, ksplit, Bm, ldb, transb, C, ldc,
                 bias, resid, ldr, K, alpha, flags,
                 blockIdx.y * 128, blockIdx.x * 128);
}

__global__ __launch_bounds__(256, 2)
void gemm_tf32_m64(const float* __restrict__ A, int lda,
               const float* __restrict__ A2, int lda2, int ksplit,
               const float* __restrict__ Bm, int ldb, int transb,
               float* __restrict__ C, int ldc,
               const float* __restrict__ bias,
               const float* __restrict__ resid, int ldr,
               int K, float alpha, int flags)
{
    gemm_body<2>(A, lda, A2, lda2, ksplit, Bm, ldb, transb, C, ldc,
                 bias, resid, ldr, K, alpha, flags,
                 blockIdx.y * 64, blockIdx.x * 128);
}

// ---- batched 4x (512x512x256) precompute GEMM: z selects params ----
struct GemmEntry { const float* A; const float* Bm; float* C; int ldb, transb, ldc; float alpha; };
struct GemmBatch4 { GemmEntry e[4]; };

__global__ __launch_bounds__(256, 2)
void gemm_batch4(GemmBatch4 p)
{
    const GemmEntry& e = p.e[blockIdx.z];
    gemm_body<4>(e.A, 512, nullptr, 0, 0, e.Bm, e.ldb, e.transb, e.C, e.ldc,
                 nullptr, nullptr, 0, 256, e.alpha, 0,
                 blockIdx.y * 128, blockIdx.x * 128);
}

// ---------------- flash attention: single pass over seq, online softmax ----
// 256 threads/CTA, one CTA per batch row. 4 chunks of 16 rows, cp.async
// double-buffered (2 x 32KB). 3 syncthreads per chunk.
#define CHUNK 16
#define CHUNK_FLOATS (CHUNK * D_)          // 8192
#define ATTN_SMEM (2 * CHUNK_FLOATS * 4)   // 64 KB

__global__ __launch_bounds__(256)
void attention_kernel(const float* __restrict__ seq,
                      const void* __restrict__ mask,
                      const float* __restrict__ qt,   // [B,1024]
                      float* __restrict__ ctx,        // [B,1024]
                      float* __restrict__ wout)       // [B,64]
{
    extern __shared__ float s_buf[];       // [2][CHUNK_FLOATS]
    __shared__ float s_all[128];           // raw scores, both heads
    __shared__ float s_m[2], s_l[2], s_f[2], s_e[2][CHUNK];
    __shared__ unsigned char s_mask[64];

    const int b = blockIdx.x, tid = threadIdx.x;
    const int warp = tid >> 5, lane = tid & 31;
    const float* sb = seq + (size_t)b * N_ * D_;

    // q fragments in registers (lane-strided float4, reused across all chunks)
    float4 q0f[4], q1f[4];
    {
        const float4* q0p = (const float4*)(qt + (size_t)b * 1024);
        const float4* q1p = q0p + 128;
#pragma unroll
        for (int i = 0; i < 4; i++) {
            q0f[i] = q0p[lane + 32 * i];
            q1f[i] = q1p[lane + 32 * i];
        }
    }

    auto stage = [&](int c, int buf) {
        float* dst = s_buf + buf * CHUNK_FLOATS;
        const float* src = sb + c * CHUNK_FLOATS;
#pragma unroll
        for (int i = 0; i < 8; i++) {
            const int e = (tid + 256 * i) * 4;
            cp16(dst + e, src + e);
        }
        asm volatile("cp.async.commit_group;" ::: "memory");
    };

    stage(0, 0);

    if (tid < 64) {
        unsigned int mv;
        if (g_mask_word) mv = ((const unsigned int*)mask)[(size_t)b * N_ + tid];
        else             mv = ((const unsigned char*)mask)[(size_t)b * N_ + tid];
        s_mask[tid] = (mv != 0u) ? 1 : 0;
    }
    if (tid < 2) { s_m[tid] = -3e38f; s_l[tid] = 0.f; }
    __syncthreads();   // s_mask / s_m init visible

    float a00 = 0.f, a01 = 0.f, a10 = 0.f, a11 = 0.f;

    for (int c = 0; c < 4; c++) {
        const int buf = c & 1;
        asm volatile("cp.async.wait_group 0;" ::: "memory");
        __syncthreads();          // buffer c ready; also retires accum of c-1
        if (c < 3) stage(c + 1, buf ^ 1);

        const float* rows = s_buf + buf * CHUNK_FLOATS;

        // scores: warp w handles chunk rows 2w, 2w+1 (both heads)
#pragma unroll
        for (int rr = 0; rr < 2; rr++) {
            const int k = 2 * warp + rr;
            const float4* r4 = (const float4*)(rows + k * D_);
            float a0 = 0.f, a1 = 0.f;
#pragma unroll
            for (int i = 0; i < 4; i++) {
                float4 s = r4[lane + 32 * i];
                a0 += s.x * q0f[i].x + s.y * q0f[i].y + s.z * q0f[i].z + s.w * q0f[i].w;
                a1 += s.x * q1f[i].x + s.y * q1f[i].y + s.z * q1f[i].z + s.w * q1f[i].w;
            }
#pragma unroll
            for (int o = 16; o; o >>= 1) {
                a0 += __shfl_xor_sync(0xffffffffu, a0, o);
                a1 += __shfl_xor_sync(0xffffffffu, a1, o);
            }
            if (lane == 0) {
                const int kg = c * CHUNK + k;
                const bool mk = s_mask[kg] != 0;
                s_all[kg]      = mk ? -1e10f : a0;
                s_all[64 + kg] = mk ? -1e10f : a1;
            }
        }
        __syncthreads();

        // online softmax update (warp 0 -> head 0, warp 1 -> head 1)
        if (warp < 2) {
            const int h = warp;
            float s = (lane < CHUNK) ? s_all[h * 64 + c * CHUNK + lane] : -3e38f;
            float cm = s;
#pragma unroll
            for (int o = 16; o; o >>= 1) cm = fmaxf(cm, __shfl_xor_sync(0xffffffffu, cm, o));
            const float m_old = s_m[h];
            const float m_new = fmaxf(m_old, cm);
            float e = (lane < CHUNK) ? __expf(s - m_new) : 0.f;
            float se = e;
#pragma unroll
            for (int o = 16; o; o >>= 1) se += __shfl_xor_sync(0xffffffffu, se, o);
            if (lane < CHUNK) s_e[h][lane] = e;
            if (lane == 0) {
                const float f = __expf(m_old - m_new);
                s_f[h] = f; s_m[h] = m_new;
                s_l[h] = s_l[h] * f + se;
            }
        }
        __syncthreads();

        // accumulate: thread owns cols (2*tid, 2*tid+1). No trailing sync —
        // next iteration's wait+sync orders buffer reuse.
        const float f0 = s_f[0], f1 = s_f[1];
        a00 *= f0; a01 *= f0; a10 *= f1; a11 *= f1;
        const float2* rows2 = (const float2*)rows;
#pragma unroll
        for (int k = 0; k < CHUNK; k++) {
            float2 v = rows2[k * 256 + tid];
            const float e0 = s_e[0][k], e1 = s_e[1][k];
            a00 += e0 * v.x; a01 += e0 * v.y;
            a10 += e1 * v.x; a11 += e1 * v.y;
        }
    }

    const float inv0 = 1.f / s_l[0], inv1 = 1.f / s_l[1];
    float2* orow = (float2*)(ctx + (size_t)b * 1024);
    orow[tid]       = make_float2(a00 * inv0, a01 * inv0);
    orow[256 + tid] = make_float2(a10 * inv1, a11 * inv1);

    if (tid < 64) {
        const float m0 = s_m[0], m1 = s_m[1];
        const float at0 = __expf(s_all[tid]      - m0) * inv0;
        const float at1 = __expf(s_all[64 + tid] - m1) * inv1;
        wout[(size_t)b * 64 + tid] = 0.5f * (at0 + at1);
    }
}

// ---------------- layernorm ----------------
__global__ __launch_bounds__(128)
void ln_kernel(const float* __restrict__ x, const float* __restrict__ gam,
               const float* __restrict__ bet, float* __restrict__ y)
{
    const int b = blockIdx.x, tid = threadIdx.x;
    const float* row = x + (size_t)b * 512;
    float v[4]; float s = 0.f;
#pragma unroll
    for (int j = 0; j < 4; j++) { v[j] = row[tid + 128 * j]; s += v[j]; }
    __shared__ float red[4];
#pragma unroll
    for (int o = 16; o; o >>= 1) s += __shfl_xor_sync(0xffffffffu, s, o);
    if ((tid & 31) == 0) red[tid >> 5] = s;
    __syncthreads();
    s = red[0] + red[1] + red[2] + red[3];
    const float mu = s * (1.f / 512.f);
    float var = 0.f;
#pragma unroll
    for (int j = 0; j < 4; j++) { float d = v[j] - mu; var += d * d; }
    __syncthreads();
#pragma unroll
    for (int o = 16; o; o >>= 1) var += __shfl_xor_sync(0xffffffffu, var, o);
    if ((tid & 31) == 0) red[tid >> 5] = var;
    __syncthreads();
    var = (red[0] + red[1] + red[2] + red[3]) * (1.f / 512.f);
    const float rs = rsqrtf(var + 1e-5f);
#pragma unroll
    for (int j = 0; j < 4; j++) {
        const int c = tid + 128 * j;
        y[(size_t)b * 512 + c] = gam[c] * (v[j] - mu) * rs + bet[c];
    }
}

// ---------------- launch ----------------
extern "C" void kernel_launch(void* const* d_in, const int* in_sizes, int n_in,
                              void* d_out, int out_size)
{
    const float* src  = (const float*)d_in[0];
    const float* seq  = (const float*)d_in[1];
    const void*  mask = d_in[2];
    const float* Wq   = (const float*)d_in[3];
    const float* Wk   = (const float*)d_in[4];
    const float* Wv   = (const float*)d_in[5];
    const float* Wo   = (const float*)d_in[6];
    const float* bo   = (const float*)d_in[7];
    const float* ln_g = (const float*)d_in[8];
    const float* ln_b = (const float*)d_in[9];
    const float* W1   = (const float*)d_in[10];
    const float* b1   = (const float*)d_in[11];
    const float* W2   = (const float*)d_in[12];
    const float* b2   = (const float*)d_in[13];
    float* y    = (float*)d_out;                       // [B, 512]
    float* wout = (float*)d_out + (size_t)B_ * 512;    // [B, 64]

    float *Ck, *Cv, *QT, *CTX, *PROJ, *LN, *H1;
    cudaGetSymbolAddress((void**)&Ck,   g_Ck);
    cudaGetSymbolAddress((void**)&Cv,   g_Cv);
    cudaGetSymbolAddress((void**)&QT,   g_QT);
    cudaGetSymbolAddress((void**)&CTX,  g_CTX);
    cudaGetSymbolAddress((void**)&PROJ, g_PROJ);
    cudaGetSymbolAddress((void**)&LN,   g_LN);
    cudaGetSymbolAddress((void**)&H1,   g_H1);

    cudaFuncSetAttribute(gemm_tf32_m128,
                         cudaFuncAttributeMaxDynamicSharedMemorySize, GEMM_SMEM_MF(4));
    cudaFuncSetAttribute(gemm_tf32_m64,
                         cudaFuncAttributeMaxDynamicSharedMemorySize, GEMM_SMEM_MF(2));
    cudaFuncSetAttribute(gemm_batch4,
                         cudaFuncAttributeMaxDynamicSharedMemorySize, GEMM_SMEM_MF(4));
    cudaFuncSetAttribute(attention_kernel,
                         cudaFuncAttributeMaxDynamicSharedMemorySize, ATTN_SMEM);

    dim3 blk(256);

    detect_mask_kernel<<<1, 256>>>((const unsigned int*)mask);

    // Batched precompute: Ck_h = Wq_h @ Wk_h^T / 16 ; Cv_h = Wv_h @ Wo[hrows,:]
    GemmBatch4 pb;
    pb.e[0] = { Wq,       Wk,                         Ck,                       512, 1, 1024, 1.f / 16.f };
    pb.e[1] = { Wq + 256, Wk + 256,                   Ck + 512,                 512, 1, 1024, 1.f / 16.f };
    pb.e[2] = { Wv,       Wo,                         Cv,                       512, 0, 512,  1.f };
    pb.e[3] = { Wv + 256, Wo + (size_t)256 * 512,     Cv + (size_t)512 * 512,   512, 0, 512,  1.f };
    gemm_batch4<<<dim3(4, 4, 4), blk, GEMM_SMEM_MF(4)>>>(pb);

    // QT = src @ Ck   (4096 x 1024, K=512), 128-row tiles (256 CTAs)
    gemm_tf32_m128<<<dim3(8, 32), blk, GEMM_SMEM_MF(4)>>>(src, 512, nullptr, 0, 0,
                                    Ck, 1024, 0, QT, 1024,
                                    nullptr, nullptr, 0, 512, 1.f, 0);
    // Flash attention (single pass over seq)
    attention_kernel<<<B_, 256, ATTN_SMEM>>>(seq, mask, QT, CTX, wout);
    // PROJ = CTX @ Cv + bo + src   (4096 x 512, K=1024), 64-row tiles (256 CTAs)
    gemm_tf32_m64<<<dim3(4, 64), blk, GEMM_SMEM_MF(2)>>>(CTX, 1024, nullptr, 0, 0,
                                    Cv, 512, 0, PROJ, 512,
                                    bo, src, 512, 1024, 1.f, FLAG_BIAS | FLAG_RESID);
    // LayerNorm
    ln_kernel<<<B_, 128>>>(PROJ, ln_g, ln_b, LN);
    // H1 = relu([LN | src] @ W1 + b1)   split-A, K=1024
    gemm_tf32_m64<<<dim3(4, 64), blk, GEMM_SMEM_MF(2)>>>(LN, 512, src, 512, 512,
                                    W1, 512, 0, H1, 512,
                                    b1, nullptr, 0, 1024, 1.f,
                                    FLAG_BIAS | FLAG_RELU);
    // y = H1 @ W2 + b2
    gemm_tf32_m64<<<dim3(4, 64), blk, GEMM_SMEM_MF(2)>>>(H1, 512, nullptr, 0, 0,
                                    W2, 512, 0, y, 512,
                                    b2, nullptr, 0, 512, 1.f, FLAG_BIAS);
}

// round 10
// speedup vs baseline: 5.7924x; 1.2350x over previous
#include <cuda_runtime.h>
#include <cuda_fp16.h>
#include <cstdint>

// Shapes (fixed for this problem)
#define B_ 4096
#define N_ 64
#define D_ 512
#define H_ 2
#define DK_ 256

// ---------------- scratch (static device arrays; no allocs) ----------------
__device__ __align__(16) __half g_src_h[(size_t)B_ * 512];
__device__ __align__(16) __half g_Wq_h[512 * 512];
__device__ __align__(16) __half g_Wk_h[512 * 512];
__device__ __align__(16) __half g_Wv_h[512 * 512];
__device__ __align__(16) __half g_WoT_h[512 * 512];          // Wo^T
__device__ __align__(16) __half g_W1T_h[512 * 1024];         // W1^T
__device__ __align__(16) __half g_W2T_h[512 * 512];          // W2^T
__device__ __align__(16) __half g_CkT[1024 * 512];           // CkT[c][i]
__device__ __align__(16) __half g_CvT[512 * 1024];           // CvT[j][c]
__device__ __align__(16) float  g_QT[(size_t)B_ * 1024];
__device__ __align__(16) __half g_CTX[(size_t)B_ * 1024];
__device__ __align__(16) float  g_PROJ[(size_t)B_ * 512];
__device__ __align__(16) __half g_LN[(size_t)B_ * 512];
__device__ __align__(16) __half g_H1[(size_t)B_ * 512];
__device__ int g_mask_word;   // 1 = 4-byte mask elements, 0 = 1-byte

// ---------------- helpers ----------------
__device__ __forceinline__ void cp16(void* s, const void* g)
{
    uint32_t sa = (uint32_t)__cvta_generic_to_shared(s);
    asm volatile("cp.async.cg.shared.global [%0], [%1], 16;" :: "r"(sa), "l"(g));
}

// ---------------- mask dtype detection ----------------
__global__ void detect_mask_kernel(const unsigned int* __restrict__ m)
{
    __shared__ int bad;
    if (threadIdx.x == 0) bad = 0;
    __syncthreads();
    unsigned int w = m[threadIdx.x];
    if (!(w == 0u || w == 1u || w == 0x3F800000u)) atomicOr(&bad, 1);
    __syncthreads();
    if (threadIdx.x == 0) g_mask_word = bad ? 0 : 1;
}

// ---------------- pre-pass: fp16 copies + transposes ----------------
struct C16Entry { const float4* s; __half2* d; int n4; };
struct C16Batch { C16Entry e[4]; };
__global__ __launch_bounds__(256)
void cvt16_kernel(C16Batch p)
{
    const C16Entry& e = p.e[blockIdx.z];
    for (int i = blockIdx.x * 256 + threadIdx.x; i < e.n4; i += gridDim.x * 256) {
        float4 v = e.s[i];
        e.d[2 * i]     = __floats2half2_rn(v.x, v.y);
        e.d[2 * i + 1] = __floats2half2_rn(v.z, v.w);
    }
}

struct TrEntry { const float* s; __half* d; int rows, cols; };
struct TrBatch { TrEntry e[3]; };
__global__ __launch_bounds__(256)
void transpose_cvt_kernel(TrBatch p)
{
    const TrEntry& e = p.e[blockIdx.z];
    const int c0 = blockIdx.x * 32, r0 = blockIdx.y * 32;
    if (c0 >= e.cols || r0 >= e.rows) return;
    __shared__ float t[32][33];
    const int x = threadIdx.x & 31, y = threadIdx.x >> 5;  // 32 x 8
#pragma unroll
    for (int j = 0; j < 32; j += 8)
        t[y + j][x] = e.s[(size_t)(r0 + y + j) * e.cols + c0 + x];
    __syncthreads();
#pragma unroll
    for (int j = 0; j < 32; j += 8)
        e.d[(size_t)(c0 + y + j) * e.rows + r0 + x] = __float2half_rn(t[x][y + j]);
}

// ---------------- fp16 tensor-core GEMM (cp.async 3-stage pipeline) ----------
// C[M,N] = alpha * A@B^T (+bias)(+resid)(relu)(out16). All operands fp16,
// B pre-transposed to [n][k]. Tiles (MF*32)x128x32, 256 thr, 8 warps (2x4),
// warp tile (MF*16)x32 via mma.m16n8k16 f16 (fp32 accum).
#define FLAG_BIAS  1
#define FLAG_RELU  2
#define FLAG_RESID 4
#define FLAG_OUT16 8

#define A_STRIDE_H 40                          // halves per SMEM row (32 used)
#define BBUF_H (128 * A_STRIDE_H)
#define GEMM_SMEM_MF(MF) (3 * ((MF) * 32 * A_STRIDE_H + BBUF_H) * 2)

template<int MF>   // CTA rows = MF*32
__device__ __forceinline__ void gemm_body(
    const __half* __restrict__ A, int lda,
    const __half* __restrict__ A2, int lda2, int ksplit,
    const __half* __restrict__ Bm, int ldb,
    void* __restrict__ C, int ldc,
    const float* __restrict__ bias,
    const float* __restrict__ resid, int ldr,
    int K, float alpha, int flags, int bm, int bn)
{
    constexpr int ABUF = MF * 32 * A_STRIDE_H;
    extern __shared__ __half smh[];
    __half* Asf = smh;                    // [3][MF*32 * A_STRIDE_H]
    __half* Bsf = smh + 3 * ABUF;         // [3][128 * A_STRIDE_H]

    const int tid = threadIdx.x;
    const int warp = tid >> 5, lane = tid & 31;
    const int wm = warp >> 2, wn = warp & 3;
    const int gid = lane >> 2, tig = lane & 3;

    float c[MF][4][4];
#pragma unroll
    for (int i = 0; i < MF; i++)
#pragma unroll
        for (int j = 0; j < 4; j++)
#pragma unroll
            for (int r = 0; r < 4; r++) c[i][j][r] = 0.f;

    const int KT = K >> 5;

    auto stage = [&](int kt, int slot) {
        const int k0 = kt * 32;
        __half* As = Asf + slot * ABUF;
        __half* Bs = Bsf + slot * BBUF_H;
        // A tile: MF*32 rows x 64B (4 x cp16 per row) = MF*128 chunks
#pragma unroll
        for (int j = 0; j < MF / 2; j++) {
            const int i = tid + 256 * j;
            const int row = i >> 2, c16 = i & 3;
            const int kg = k0 + c16 * 8;
            const __half* ap = (A2 != nullptr && kg >= ksplit)
                ? (A2 + (size_t)(bm + row) * lda2 + (kg - ksplit))
                : (A  + (size_t)(bm + row) * lda  + kg);
            cp16(As + row * A_STRIDE_H + c16 * 8, ap);
        }
        // B tile: 128 rows (n) x 64B = 512 chunks
#pragma unroll
        for (int j = 0; j < 2; j++) {
            const int i = tid + 256 * j;
            const int row = i >> 2, c16 = i & 3;
            cp16(Bs + row * A_STRIDE_H + c16 * 8,
                 Bm + (size_t)(bn + row) * ldb + k0 + c16 * 8);
        }
        asm volatile("cp.async.commit_group;" ::: "memory");
    };

    stage(0, 0);
    if (KT > 1) stage(1, 1);

    int slot = 0;
    for (int kt = 0; kt < KT; kt++) {
        asm volatile("cp.async.wait_group 1;" ::: "memory");
        __syncthreads();
        if (kt + 2 < KT) {
            int ns = slot + 2; if (ns >= 3) ns -= 3;
            stage(kt + 2, ns);
        }

        const __half* As = Asf + slot * ABUF;
        const __half* Bs = Bsf + slot * BBUF_H;
#pragma unroll
        for (int ks = 0; ks < 2; ks++) {
            uint32_t a[MF][4], b[4][2];
#pragma unroll
            for (int mf = 0; mf < MF; mf++) {
                const int r = wm * (MF * 16) + mf * 16 + gid;
                const __half* ar = As + r * A_STRIDE_H + ks * 16 + 2 * tig;
                a[mf][0] = *(const uint32_t*)ar;
                a[mf][1] = *(const uint32_t*)(ar + 8 * A_STRIDE_H);
                a[mf][2] = *(const uint32_t*)(ar + 8);
                a[mf][3] = *(const uint32_t*)(ar + 8 * A_STRIDE_H + 8);
            }
#pragma unroll
            for (int nf = 0; nf < 4; nf++) {
                const int cn = wn * 32 + nf * 8 + gid;
                const __half* br = Bs + cn * A_STRIDE_H + ks * 16 + 2 * tig;
                b[nf][0] = *(const uint32_t*)br;
                b[nf][1] = *(const uint32_t*)(br + 8);
            }
#pragma unroll
            for (int mf = 0; mf < MF; mf++)
#pragma unroll
                for (int nf = 0; nf < 4; nf++)
                    asm volatile(
                        "mma.sync.aligned.m16n8k16.row.col.f32.f16.f16.f32 "
                        "{%0,%1,%2,%3}, {%4,%5,%6,%7}, {%8,%9}, {%0,%1,%2,%3};"
                        : "+f"(c[mf][nf][0]), "+f"(c[mf][nf][1]),
                          "+f"(c[mf][nf][2]), "+f"(c[mf][nf][3])
                        : "r"(a[mf][0]), "r"(a[mf][1]), "r"(a[mf][2]), "r"(a[mf][3]),
                          "r"(b[nf][0]), "r"(b[nf][1]));
        }
        slot++; if (slot == 3) slot = 0;
    }

    // ---- epilogue ----
#pragma unroll
    for (int mf = 0; mf < MF; mf++) {
        const int r0 = bm + wm * (MF * 16) + mf * 16 + gid;
#pragma unroll
        for (int nf = 0; nf < 4; nf++) {
            const int cn = bn + wn * 32 + nf * 8 + tig * 2;
#pragma unroll
            for (int half = 0; half < 2; half++) {
                const int row = r0 + half * 8;
                float v0 = c[mf][nf][half * 2 + 0] * alpha;
                float v1 = c[mf][nf][half * 2 + 1] * alpha;
                if (flags & FLAG_BIAS)  { v0 += bias[cn]; v1 += bias[cn + 1]; }
                if (flags & FLAG_RESID) {
                    v0 += resid[(size_t)row * ldr + cn];
                    v1 += resid[(size_t)row * ldr + cn + 1];
                }
                if (flags & FLAG_RELU)  { v0 = fmaxf(v0, 0.f); v1 = fmaxf(v1, 0.f); }
                if (flags & FLAG_OUT16) {
                    *(__half2*)((__half*)C + (size_t)row * ldc + cn) =
                        __floats2half2_rn(v0, v1);
                } else {
                    float* crow = (float*)C + (size_t)row * ldc + cn;
                    crow[0] = v0; crow[1] = v1;
                }
            }
        }
    }
}

__global__ __launch_bounds__(256, 2)
void gemm_h_m128(const __half* __restrict__ A, int lda,
                 const __half* __restrict__ A2, int lda2, int ksplit,
                 const __half* __restrict__ Bm, int ldb,
                 void* __restrict__ C, int ldc,
                 const float* __restrict__ bias,
                 const float* __restrict__ resid, int ldr,
                 int K, float alpha, int flags)
{
    gemm_body<4>(A, lda, A2, lda2, ksplit, Bm, ldb, C, ldc,
                 bias, resid, ldr, K, alpha, flags,
                 blockIdx.y * 128, blockIdx.x * 128);
}

__global__ __launch_bounds__(256, 2)
void gemm_h_m64(const __half* __restrict__ A, int lda,
                const __half* __restrict__ A2, int lda2, int ksplit,
                const __half* __restrict__ Bm, int ldb,
                void* __restrict__ C, int ldc,
                const float* __restrict__ bias,
                const float* __restrict__ resid, int ldr,
                int K, float alpha, int flags)
{
    gemm_body<2>(A, lda, A2, lda2, ksplit, Bm, ldb, C, ldc,
                 bias, resid, ldr, K, alpha, flags,
                 blockIdx.y * 64, blockIdx.x * 128);
}

// ---- batched 4x (512x512x256) precompute GEMM -> fp16 out ----
struct GemmEntry { const __half* A; const __half* Bm; __half* C; int ldc; float alpha; };
struct GemmBatch4 { GemmEntry e[4]; };

__global__ __launch_bounds__(256, 2)
void gemm_h_b4(GemmBatch4 p)
{
    const GemmEntry& e = p.e[blockIdx.z];
    gemm_body<4>(e.A, 512, nullptr, 0, 0, e.Bm, 512, e.C, e.ldc,
                 nullptr, nullptr, 0, 256, e.alpha, FLAG_OUT16,
                 blockIdx.y * 128, blockIdx.x * 128);
}

// ---------------- flash attention: single pass over seq, online softmax ----
#define CHUNK 16
#define CHUNK_FLOATS (CHUNK * D_)
#define ATTN_SMEM (2 * CHUNK_FLOATS * 4)   // 64 KB

__global__ __launch_bounds__(256)
void attention_kernel(const float* __restrict__ seq,
                      const void* __restrict__ mask,
                      const float* __restrict__ qt,   // [B,1024] fp32
                      __half* __restrict__ ctx,       // [B,1024] fp16
                      float* __restrict__ wout)       // [B,64]
{
    extern __shared__ float s_buf[];
    __shared__ float s_all[128];
    __shared__ float s_m[2], s_l[2], s_f[2], s_e[2][CHUNK];
    __shared__ unsigned char s_mask[64];

    const int b = blockIdx.x, tid = threadIdx.x;
    const int warp = tid >> 5, lane = tid & 31;
    const float* sbp = seq + (size_t)b * N_ * D_;

    float4 q0f[4], q1f[4];
    {
        const float4* q0p = (const float4*)(qt + (size_t)b * 1024);
        const float4* q1p = q0p + 128;
#pragma unroll
        for (int i = 0; i < 4; i++) {
            q0f[i] = q0p[lane + 32 * i];
            q1f[i] = q1p[lane + 32 * i];
        }
    }

    auto stage = [&](int c, int buf) {
        float* dst = s_buf + buf * CHUNK_FLOATS;
        const float* src = sbp + c * CHUNK_FLOATS;
#pragma unroll
        for (int i = 0; i < 8; i++) {
            const int e = (tid + 256 * i) * 4;
            cp16(dst + e, src + e);
        }
        asm volatile("cp.async.commit_group;" ::: "memory");
    };

    stage(0, 0);

    if (tid < 64) {
        unsigned int mv;
        if (g_mask_word) mv = ((const unsigned int*)mask)[(size_t)b * N_ + tid];
        else             mv = ((const unsigned char*)mask)[(size_t)b * N_ + tid];
        s_mask[tid] = (mv != 0u) ? 1 : 0;
    }
    if (tid < 2) { s_m[tid] = -3e38f; s_l[tid] = 0.f; }
    __syncthreads();

    float a00 = 0.f, a01 = 0.f, a10 = 0.f, a11 = 0.f;

    for (int c = 0; c < 4; c++) {
        const int buf = c & 1;
        asm volatile("cp.async.wait_group 0;" ::: "memory");
        __syncthreads();
        if (c < 3) stage(c + 1, buf ^ 1);

        const float* rows = s_buf + buf * CHUNK_FLOATS;

#pragma unroll
        for (int rr = 0; rr < 2; rr++) {
            const int k = 2 * warp + rr;
            const float4* r4 = (const float4*)(rows + k * D_);
            float a0 = 0.f, a1 = 0.f;
#pragma unroll
            for (int i = 0; i < 4; i++) {
                float4 s = r4[lane + 32 * i];
                a0 += s.x * q0f[i].x + s.y * q0f[i].y + s.z * q0f[i].z + s.w * q0f[i].w;
                a1 += s.x * q1f[i].x + s.y * q1f[i].y + s.z * q1f[i].z + s.w * q1f[i].w;
            }
#pragma unroll
            for (int o = 16; o; o >>= 1) {
                a0 += __shfl_xor_sync(0xffffffffu, a0, o);
                a1 += __shfl_xor_sync(0xffffffffu, a1, o);
            }
            if (lane == 0) {
                const int kg = c * CHUNK + k;
                const bool mk = s_mask[kg] != 0;
                s_all[kg]      = mk ? -1e10f : a0;
                s_all[64 + kg] = mk ? -1e10f : a1;
            }
        }
        __syncthreads();

        if (warp < 2) {
            const int h = warp;
            float s = (lane < CHUNK) ? s_all[h * 64 + c * CHUNK + lane] : -3e38f;
            float cm = s;
#pragma unroll
            for (int o = 16; o; o >>= 1) cm = fmaxf(cm, __shfl_xor_sync(0xffffffffu, cm, o));
            const float m_old = s_m[h];
            const float m_new = fmaxf(m_old, cm);
            float e = (lane < CHUNK) ? __expf(s - m_new) : 0.f;
            float se = e;
#pragma unroll
            for (int o = 16; o; o >>= 1) se += __shfl_xor_sync(0xffffffffu, se, o);
            if (lane < CHUNK) s_e[h][lane] = e;
            if (lane == 0) {
                const float f = __expf(m_old - m_new);
                s_f[h] = f; s_m[h] = m_new;
                s_l[h] = s_l[h] * f + se;
            }
        }
        __syncthreads();

        const float f0 = s_f[0], f1 = s_f[1];
        a00 *= f0; a01 *= f0; a10 *= f1; a11 *= f1;
        const float2* rows2 = (const float2*)rows;
#pragma unroll
        for (int k = 0; k < CHUNK; k++) {
            float2 v = rows2[k * 256 + tid];
            const float e0 = s_e[0][k], e1 = s_e[1][k];
            a00 += e0 * v.x; a01 += e0 * v.y;
            a10 += e1 * v.x; a11 += e1 * v.y;
        }
    }

    const float inv0 = 1.f / s_l[0], inv1 = 1.f / s_l[1];
    // ctx is a downstream GEMM operand -> fp16
    __half2* orow = (__half2*)(ctx + (size_t)b * 1024);
    orow[tid]       = __floats2half2_rn(a00 * inv0, a01 * inv0);
    orow[256 + tid] = __floats2half2_rn(a10 * inv1, a11 * inv1);

    if (tid < 64) {
        const float m0 = s_m[0], m1 = s_m[1];
        const float at0 = __expf(s_all[tid]      - m0) * inv0;
        const float at1 = __expf(s_all[64 + tid] - m1) * inv1;
        wout[(size_t)b * 64 + tid] = 0.5f * (at0 + at1);
    }
}

// ---------------- layernorm (fp16 out: GEMM operand) ----------------
__global__ __launch_bounds__(128)
void ln_kernel(const float* __restrict__ x, const float* __restrict__ gam,
               const float* __restrict__ bet, __half* __restrict__ y)
{
    const int b = blockIdx.x, tid = threadIdx.x;
    const float* row = x + (size_t)b * 512;
    float v[4]; float s = 0.f;
#pragma unroll
    for (int j = 0; j < 4; j++) { v[j] = row[tid + 128 * j]; s += v[j]; }
    __shared__ float red[4];
#pragma unroll
    for (int o = 16; o; o >>= 1) s += __shfl_xor_sync(0xffffffffu, s, o);
    if ((tid & 31) == 0) red[tid >> 5] = s;
    __syncthreads();
    s = red[0] + red[1] + red[2] + red[3];
    const float mu = s * (1.f / 512.f);
    float var = 0.f;
#pragma unroll
    for (int j = 0; j < 4; j++) { float d = v[j] - mu; var += d * d; }
    __syncthreads();
#pragma unroll
    for (int o = 16; o; o >>= 1) var += __shfl_xor_sync(0xffffffffu, var, o);
    if ((tid & 31) == 0) red[tid >> 5] = var;
    __syncthreads();
    var = (red[0] + red[1] + red[2] + red[3]) * (1.f / 512.f);
    const float rs = rsqrtf(var + 1e-5f);
#pragma unroll
    for (int j = 0; j < 4; j++) {
        const int c = tid + 128 * j;
        y[(size_t)b * 512 + c] = __float2half_rn(gam[c] * (v[j] - mu) * rs + bet[c]);
    }
}

// ---------------- launch ----------------
extern "C" void kernel_launch(void* const* d_in, const int* in_sizes, int n_in,
                              void* d_out, int out_size)
{
    const float* src  = (const float*)d_in[0];
    const float* seq  = (const float*)d_in[1];
    const void*  mask = d_in[2];
    const float* Wq   = (const float*)d_in[3];
    const float* Wk   = (const float*)d_in[4];
    const float* Wv   = (const float*)d_in[5];
    const float* Wo   = (const float*)d_in[6];
    const float* bo   = (const float*)d_in[7];
    const float* ln_g = (const float*)d_in[8];
    const float* ln_b = (const float*)d_in[9];
    const float* W1   = (const float*)d_in[10];
    const float* b1   = (const float*)d_in[11];
    const float* W2   = (const float*)d_in[12];
    const float* b2   = (const float*)d_in[13];
    float* y    = (float*)d_out;                       // [B, 512]
    float* wout = (float*)d_out + (size_t)B_ * 512;    // [B, 64]

    __half *src_h, *Wq_h, *Wk_h, *Wv_h, *WoT, *W1T, *W2T, *CkT, *CvT, *CTX, *LN, *H1;
    float *QT, *PROJ;
    cudaGetSymbolAddress((void**)&src_h, g_src_h);
    cudaGetSymbolAddress((void**)&Wq_h,  g_Wq_h);
    cudaGetSymbolAddress((void**)&Wk_h,  g_Wk_h);
    cudaGetSymbolAddress((void**)&Wv_h,  g_Wv_h);
    cudaGetSymbolAddress((void**)&WoT,   g_WoT_h);
    cudaGetSymbolAddress((void**)&W1T,   g_W1T_h);
    cudaGetSymbolAddress((void**)&W2T,   g_W2T_h);
    cudaGetSymbolAddress((void**)&CkT,   g_CkT);
    cudaGetSymbolAddress((void**)&CvT,   g_CvT);
    cudaGetSymbolAddress((void**)&QT,    g_QT);
    cudaGetSymbolAddress((void**)&CTX,   g_CTX);
    cudaGetSymbolAddress((void**)&PROJ,  g_PROJ);
    cudaGetSymbolAddress((void**)&LN,    g_LN);
    cudaGetSymbolAddress((void**)&H1,    g_H1);

    cudaFuncSetAttribute(gemm_h_m128,
                         cudaFuncAttributeMaxDynamicSharedMemorySize, GEMM_SMEM_MF(4));
    cudaFuncSetAttribute(gemm_h_m64,
                         cudaFuncAttributeMaxDynamicSharedMemorySize, GEMM_SMEM_MF(2));
    cudaFuncSetAttribute(gemm_h_b4,
                         cudaFuncAttributeMaxDynamicSharedMemorySize, GEMM_SMEM_MF(4));
    cudaFuncSetAttribute(attention_kernel,
                         cudaFuncAttributeMaxDynamicSharedMemorySize, ATTN_SMEM);

    dim3 blk(256);

    detect_mask_kernel<<<1, 256>>>((const unsigned int*)mask);

    // pre-pass: fp16 copies (src, Wq, Wk, Wv)
    C16Batch cb;
    cb.e[0] = { (const float4*)src, (__half2*)src_h, B_ * 512 / 4 };
    cb.e[1] = { (const float4*)Wq,  (__half2*)Wq_h,  512 * 512 / 4 };
    cb.e[2] = { (const float4*)Wk,  (__half2*)Wk_h,  512 * 512 / 4 };
    cb.e[3] = { (const float4*)Wv,  (__half2*)Wv_h,  512 * 512 / 4 };
    cvt16_kernel<<<dim3(132, 1, 4), blk>>>(cb);

    // pre-pass: transposed fp16 (Wo, W1, W2)
    TrBatch tb;
    tb.e[0] = { Wo, WoT, 512, 512 };
    tb.e[1] = { W1, W1T, 1024, 512 };
    tb.e[2] = { W2, W2T, 512, 512 };
    transpose_cvt_kernel<<<dim3(16, 32, 3), blk>>>(tb);

    // precompute: CkT[h512+d][i] = (1/16) sum_k Wk[d,h256+k] Wq[i,h256+k]
    //             CvT[j][h512+i] =        sum_k WoT[j,h256+k] Wv[i,h256+k]
    GemmBatch4 pb;
    pb.e[0] = { Wk_h,       Wq_h,       CkT,                      512,  1.f / 16.f };
    pb.e[1] = { Wk_h + 256, Wq_h + 256, CkT + (size_t)512 * 512,  512,  1.f / 16.f };
    pb.e[2] = { WoT,        Wv_h,       CvT,                      1024, 1.f };
    pb.e[3] = { WoT + 256,  Wv_h + 256, CvT + 512,                1024, 1.f };
    gemm_h_b4<<<dim3(4, 4, 4), blk, GEMM_SMEM_MF(4)>>>(pb);

    // QT = src_h @ CkT^T (fp32 out)
    gemm_h_m128<<<dim3(8, 32), blk, GEMM_SMEM_MF(4)>>>(src_h, 512, nullptr, 0, 0,
                                    CkT, 512, QT, 1024,
                                    nullptr, nullptr, 0, 512, 1.f, 0);
    // flash attention (CTX fp16 out)
    attention_kernel<<<B_, 256, ATTN_SMEM>>>(seq, mask, QT, CTX, wout);
    // PROJ = CTX @ CvT^T + bo + src (fp32 out)
    gemm_h_m64<<<dim3(4, 64), blk, GEMM_SMEM_MF(2)>>>(CTX, 1024, nullptr, 0, 0,
                                    CvT, 1024, PROJ, 512,
                                    bo, src, 512, 1024, 1.f, FLAG_BIAS | FLAG_RESID);
    // LayerNorm (fp16 out)
    ln_kernel<<<B_, 128>>>(PROJ, ln_g, ln_b, LN);
    // H1 = relu([LN | src_h] @ W1T^T + b1) (fp16 out)
    gemm_h_m64<<<dim3(4, 64), blk, GEMM_SMEM_MF(2)>>>(LN, 512, src_h, 512, 512,
                                    W1T, 1024, H1, 512,
                                    b1, nullptr, 0, 1024, 1.f,
                                    FLAG_BIAS | FLAG_RELU | FLAG_OUT16);
    // y = H1 @ W2T^T + b2 (fp32 out)
    gemm_h_m64<<<dim3(4, 64), blk, GEMM_SMEM_MF(2)>>>(H1, 512, nullptr, 0, 0,
                                    W2T, 512, y, 512,
                                    b2, nullptr, 0, 512, 1.f, FLAG_BIAS);
}

// round 11
// speedup vs baseline: 6.1352x; 1.0592x over previous
#include <cuda_runtime.h>
#include <cuda_fp16.h>
#include <cstdint>

// Shapes (fixed for this problem)
#define B_ 4096
#define N_ 64
#define D_ 512
#define H_ 2
#define DK_ 256

// ---------------- scratch (static device arrays; no allocs) ----------------
__device__ __align__(16) __half g_src_h[(size_t)B_ * 512];
__device__ __align__(16) __half g_Wq_h[512 * 512];
__device__ __align__(16) __half g_Wk_h[512 * 512];
__device__ __align__(16) __half g_Wv_h[512 * 512];
__device__ __align__(16) __half g_WoT_h[512 * 512];          // Wo^T
__device__ __align__(16) __half g_W1T_h[512 * 1024];         // W1^T
__device__ __align__(16) __half g_W2T_h[512 * 512];          // W2^T
__device__ __align__(16) __half g_CkT[1024 * 512];           // CkT[c][i]
__device__ __align__(16) __half g_CvT[512 * 1024];           // CvT[j][c]
__device__ __align__(16) float  g_QT[(size_t)B_ * 1024];
__device__ __align__(16) __half g_CTX[(size_t)B_ * 1024];
__device__ __align__(16) float  g_PROJ[(size_t)B_ * 512];
__device__ __align__(16) __half g_LN[(size_t)B_ * 512];
__device__ __align__(16) __half g_H1[(size_t)B_ * 512];
__device__ int g_mask_word;   // 1 = 4-byte mask elements, 0 = 1-byte

// ---------------- helpers ----------------
__device__ __forceinline__ void cp16(void* s, const void* g)
{
    uint32_t sa = (uint32_t)__cvta_generic_to_shared(s);
    asm volatile("cp.async.cg.shared.global [%0], [%1], 16;" :: "r"(sa), "l"(g));
}
__device__ __forceinline__ void ldsm_x4(uint32_t& r0, uint32_t& r1,
                                        uint32_t& r2, uint32_t& r3, const void* p)
{
    uint32_t a = (uint32_t)__cvta_generic_to_shared(p);
    asm volatile("ldmatrix.sync.aligned.m8n8.x4.shared.b16 {%0,%1,%2,%3}, [%4];"
                 : "=r"(r0), "=r"(r1), "=r"(r2), "=r"(r3) : "r"(a));
}

// ---------------- mask dtype detection ----------------
__global__ void detect_mask_kernel(const unsigned int* __restrict__ m)
{
    __shared__ int bad;
    if (threadIdx.x == 0) bad = 0;
    __syncthreads();
    unsigned int w = m[threadIdx.x];
    if (!(w == 0u || w == 1u || w == 0x3F800000u)) atomicOr(&bad, 1);
    __syncthreads();
    if (threadIdx.x == 0) g_mask_word = bad ? 0 : 1;
}

// ---------------- pre-pass: fp16 copies + transposes ----------------
struct C16Entry { const float4* s; __half2* d; int n4; };
struct C16Batch { C16Entry e[4]; };
__global__ __launch_bounds__(256)
void cvt16_kernel(C16Batch p)
{
    const C16Entry& e = p.e[blockIdx.z];
    for (int i = blockIdx.x * 256 + threadIdx.x; i < e.n4; i += gridDim.x * 256) {
        float4 v = e.s[i];
        e.d[2 * i]     = __floats2half2_rn(v.x, v.y);
        e.d[2 * i + 1] = __floats2half2_rn(v.z, v.w);
    }
}

struct TrEntry { const float* s; __half* d; int rows, cols; };
struct TrBatch { TrEntry e[3]; };
__global__ __launch_bounds__(256)
void transpose_cvt_kernel(TrBatch p)
{
    const TrEntry& e = p.e[blockIdx.z];
    const int c0 = blockIdx.x * 32, r0 = blockIdx.y * 32;
    if (c0 >= e.cols || r0 >= e.rows) return;
    __shared__ float t[32][33];
    const int x = threadIdx.x & 31, y = threadIdx.x >> 5;  // 32 x 8
#pragma unroll
    for (int j = 0; j < 32; j += 8)
        t[y + j][x] = e.s[(size_t)(r0 + y + j) * e.cols + c0 + x];
    __syncthreads();
#pragma unroll
    for (int j = 0; j < 32; j += 8)
        e.d[(size_t)(c0 + y + j) * e.rows + r0 + x] = __float2half_rn(t[x][y + j]);
}

// ---------------- fp16 tensor-core GEMM (cp.async 3-stage, ldmatrix) --------
// C[M,N] = alpha * A@B^T (+bias)(+resid)(relu)(out16). All operands fp16,
// B pre-transposed to [n][k]. Tiles (MF*32)x128x32, 256 thr, 8 warps (2x4),
// warp tile (MF*16)x32 via mma.m16n8k16 f16 (fp32 accum).
#define FLAG_BIAS  1
#define FLAG_RELU  2
#define FLAG_RESID 4
#define FLAG_OUT16 8

#define A_STRIDE_H 40                          // halves per SMEM row (32 used)
#define BBUF_H (128 * A_STRIDE_H)
#define GEMM_SMEM_MF(MF) (3 * ((MF) * 32 * A_STRIDE_H + BBUF_H) * 2)

template<int MF>   // CTA rows = MF*32
__device__ __forceinline__ void gemm_body(
    const __half* __restrict__ A, int lda,
    const __half* __restrict__ A2, int lda2, int ksplit,
    const __half* __restrict__ Bm, int ldb,
    void* __restrict__ C, int ldc,
    const float* __restrict__ bias,
    const float* __restrict__ resid, int ldr,
    int K, float alpha, int flags, int bm, int bn)
{
    constexpr int ABUF = MF * 32 * A_STRIDE_H;
    extern __shared__ __half smh[];
    __half* Asf = smh;                    // [3][MF*32 * A_STRIDE_H]
    __half* Bsf = smh + 3 * ABUF;         // [3][128 * A_STRIDE_H]

    const int tid = threadIdx.x;
    const int warp = tid >> 5, lane = tid & 31;
    const int wm = warp >> 2, wn = warp & 3;
    const int gid = lane >> 2, tig = lane & 3;

    // ldmatrix lane addressing (halves)
    const int a_row_l = (lane & 7) + ((lane >> 3) & 1) * 8;
    const int a_col_l = ((lane >> 4) & 1) * 8;
    const int b_row_l = ((lane >> 4) & 1) * 8 + (lane & 7);
    const int b_col_l = ((lane >> 3) & 1) * 8;

    float c[MF][4][4];
#pragma unroll
    for (int i = 0; i < MF; i++)
#pragma unroll
        for (int j = 0; j < 4; j++)
#pragma unroll
            for (int r = 0; r < 4; r++) c[i][j][r] = 0.f;

    const int KT = K >> 5;

    auto stage = [&](int kt, int slot) {
        const int k0 = kt * 32;
        __half* As = Asf + slot * ABUF;
        __half* Bs = Bsf + slot * BBUF_H;
#pragma unroll
        for (int j = 0; j < MF / 2; j++) {
            const int i = tid + 256 * j;
            const int row = i >> 2, c16 = i & 3;
            const int kg = k0 + c16 * 8;
            const __half* ap = (A2 != nullptr && kg >= ksplit)
                ? (A2 + (size_t)(bm + row) * lda2 + (kg - ksplit))
                : (A  + (size_t)(bm + row) * lda  + kg);
            cp16(As + row * A_STRIDE_H + c16 * 8, ap);
        }
#pragma unroll
        for (int j = 0; j < 2; j++) {
            const int i = tid + 256 * j;
            const int row = i >> 2, c16 = i & 3;
            cp16(Bs + row * A_STRIDE_H + c16 * 8,
                 Bm + (size_t)(bn + row) * ldb + k0 + c16 * 8);
        }
        asm volatile("cp.async.commit_group;" ::: "memory");
    };

    stage(0, 0);
    if (KT > 1) stage(1, 1);

    int slot = 0;
    for (int kt = 0; kt < KT; kt++) {
        asm volatile("cp.async.wait_group 1;" ::: "memory");
        __syncthreads();
        if (kt + 2 < KT) {
            int ns = slot + 2; if (ns >= 3) ns -= 3;
            stage(kt + 2, ns);
        }

        const __half* As = Asf + slot * ABUF;
        const __half* Bs = Bsf + slot * BBUF_H;
#pragma unroll
        for (int ks = 0; ks < 2; ks++) {
            uint32_t a[MF][4], b[4][2];
#pragma unroll
            for (int mf = 0; mf < MF; mf++) {
                const int r = wm * (MF * 16) + mf * 16 + a_row_l;
                ldsm_x4(a[mf][0], a[mf][1], a[mf][2], a[mf][3],
                        As + r * A_STRIDE_H + ks * 16 + a_col_l);
            }
#pragma unroll
            for (int nfp = 0; nfp < 2; nfp++) {
                const int cn = wn * 32 + nfp * 16 + b_row_l;
                ldsm_x4(b[2 * nfp][0], b[2 * nfp][1], b[2 * nfp + 1][0], b[2 * nfp + 1][1],
                        Bs + cn * A_STRIDE_H + ks * 16 + b_col_l);
            }
#pragma unroll
            for (int mf = 0; mf < MF; mf++)
#pragma unroll
                for (int nf = 0; nf < 4; nf++)
                    asm volatile(
                        "mma.sync.aligned.m16n8k16.row.col.f32.f16.f16.f32 "
                        "{%0,%1,%2,%3}, {%4,%5,%6,%7}, {%8,%9}, {%0,%1,%2,%3};"
                        : "+f"(c[mf][nf][0]), "+f"(c[mf][nf][1]),
                          "+f"(c[mf][nf][2]), "+f"(c[mf][nf][3])
                        : "r"(a[mf][0]), "r"(a[mf][1]), "r"(a[mf][2]), "r"(a[mf][3]),
                          "r"(b[nf][0]), "r"(b[nf][1]));
        }
        slot++; if (slot == 3) slot = 0;
    }

    // ---- epilogue ----
#pragma unroll
    for (int mf = 0; mf < MF; mf++) {
        const int r0 = bm + wm * (MF * 16) + mf * 16 + gid;
#pragma unroll
        for (int nf = 0; nf < 4; nf++) {
            const int cn = bn + wn * 32 + nf * 8 + tig * 2;
#pragma unroll
            for (int half = 0; half < 2; half++) {
                const int row = r0 + half * 8;
                float v0 = c[mf][nf][half * 2 + 0] * alpha;
                float v1 = c[mf][nf][half * 2 + 1] * alpha;
                if (flags & FLAG_BIAS)  { v0 += bias[cn]; v1 += bias[cn + 1]; }
                if (flags & FLAG_RESID) {
                    v0 += resid[(size_t)row * ldr + cn];
                    v1 += resid[(size_t)row * ldr + cn + 1];
                }
                if (flags & FLAG_RELU)  { v0 = fmaxf(v0, 0.f); v1 = fmaxf(v1, 0.f); }
                if (flags & FLAG_OUT16) {
                    *(__half2*)((__half*)C + (size_t)row * ldc + cn) =
                        __floats2half2_rn(v0, v1);
                } else {
                    float* crow = (float*)C + (size_t)row * ldc + cn;
                    crow[0] = v0; crow[1] = v1;
                }
            }
        }
    }
}

__global__ __launch_bounds__(256, 2)
void gemm_h_m128(const __half* __restrict__ A, int lda,
                 const __half* __restrict__ A2, int lda2, int ksplit,
                 const __half* __restrict__ Bm, int ldb,
                 void* __restrict__ C, int ldc,
                 const float* __restrict__ bias,
                 const float* __restrict__ resid, int ldr,
                 int K, float alpha, int flags)
{
    gemm_body<4>(A, lda, A2, lda2, ksplit, Bm, ldb, C, ldc,
                 bias, resid, ldr, K, alpha, flags,
                 blockIdx.y * 128, blockIdx.x * 128);
}

__global__ __launch_bounds__(256, 2)
void gemm_h_m64(const __half* __restrict__ A, int lda,
                const __half* __restrict__ A2, int lda2, int ksplit,
                const __half* __restrict__ Bm, int ldb,
                void* __restrict__ C, int ldc,
                const float* __restrict__ bias,
                const float* __restrict__ resid, int ldr,
                int K, float alpha, int flags)
{
    gemm_body<2>(A, lda, A2, lda2, ksplit, Bm, ldb, C, ldc,
                 bias, resid, ldr, K, alpha, flags,
                 blockIdx.y * 64, blockIdx.x * 128);
}

// ---- batched 4x (512x512x256) precompute GEMM -> fp16 out ----
struct GemmEntry { const __half* A; const __half* Bm; __half* C; int ldc; float alpha; };
struct GemmBatch4 { GemmEntry e[4]; };

__global__ __launch_bounds__(256, 2)
void gemm_h_b4(GemmBatch4 p)
{
    const GemmEntry& e = p.e[blockIdx.z];
    gemm_body<4>(e.A, 512, nullptr, 0, 0, e.Bm, 512, e.C, e.ldc,
                 nullptr, nullptr, 0, 256, e.alpha, FLAG_OUT16,
                 blockIdx.y * 128, blockIdx.x * 128);
}

// ---------------- flash attention: single pass over seq, online softmax ----
#define CHUNK 16
#define CHUNK_FLOATS (CHUNK * D_)
#define ATTN_SMEM (2 * CHUNK_FLOATS * 4)   // 64 KB

__global__ __launch_bounds__(256)
void attention_kernel(const float* __restrict__ seq,
                      const void* __restrict__ mask,
                      const float* __restrict__ qt,   // [B,1024] fp32
                      __half* __restrict__ ctx,       // [B,1024] fp16
                      float* __restrict__ wout)       // [B,64]
{
    extern __shared__ float s_buf[];
    __shared__ float s_all[128];
    __shared__ float s_m[2], s_l[2], s_f[2], s_e[2][CHUNK];
    __shared__ unsigned char s_mask[64];

    const int b = blockIdx.x, tid = threadIdx.x;
    const int warp = tid >> 5, lane = tid & 31;
    const float* sbp = seq + (size_t)b * N_ * D_;

    float4 q0f[4], q1f[4];
    {
        const float4* q0p = (const float4*)(qt + (size_t)b * 1024);
        const float4* q1p = q0p + 128;
#pragma unroll
        for (int i = 0; i < 4; i++) {
            q0f[i] = q0p[lane + 32 * i];
            q1f[i] = q1p[lane + 32 * i];
        }
    }

    auto stage = [&](int c, int buf) {
        float* dst = s_buf + buf * CHUNK_FLOATS;
        const float* src = sbp + c * CHUNK_FLOATS;
#pragma unroll
        for (int i = 0; i < 8; i++) {
            const int e = (tid + 256 * i) * 4;
            cp16(dst + e, src + e);
        }
        asm volatile("cp.async.commit_group;" ::: "memory");
    };

    stage(0, 0);

    if (tid < 64) {
        unsigned int mv;
        if (g_mask_word) mv = ((const unsigned int*)mask)[(size_t)b * N_ + tid];
        else             mv = ((const unsigned char*)mask)[(size_t)b * N_ + tid];
        s_mask[tid] = (mv != 0u) ? 1 : 0;
    }
    if (tid < 2) { s_m[tid] = -3e38f; s_l[tid] = 0.f; }
    __syncthreads();

    float a00 = 0.f, a01 = 0.f, a10 = 0.f, a11 = 0.f;

    for (int c = 0; c < 4; c++) {
        const int buf = c & 1;
        asm volatile("cp.async.wait_group 0;" ::: "memory");
        __syncthreads();
        if (c < 3) stage(c + 1, buf ^ 1);

        const float* rows = s_buf + buf * CHUNK_FLOATS;

#pragma unroll
        for (int rr = 0; rr < 2; rr++) {
            const int k = 2 * warp + rr;
            const float4* r4 = (const float4*)(rows + k * D_);
            float a0 = 0.f, a1 = 0.f;
#pragma unroll
            for (int i = 0; i < 4; i++) {
                float4 s = r4[lane + 32 * i];
                a0 += s.x * q0f[i].x + s.y * q0f[i].y + s.z * q0f[i].z + s.w * q0f[i].w;
                a1 += s.x * q1f[i].x + s.y * q1f[i].y + s.z * q1f[i].z + s.w * q1f[i].w;
            }
#pragma unroll
            for (int o = 16; o; o >>= 1) {
                a0 += __shfl_xor_sync(0xffffffffu, a0, o);
                a1 += __shfl_xor_sync(0xffffffffu, a1, o);
            }
            if (lane == 0) {
                const int kg = c * CHUNK + k;
                const bool mk = s_mask[kg] != 0;
                s_all[kg]      = mk ? -1e10f : a0;
                s_all[64 + kg] = mk ? -1e10f : a1;
            }
        }
        __syncthreads();

        if (warp < 2) {
            const int h = warp;
            float s = (lane < CHUNK) ? s_all[h * 64 + c * CHUNK + lane] : -3e38f;
            float cm = s;
#pragma unroll
            for (int o = 16; o; o >>= 1) cm = fmaxf(cm, __shfl_xor_sync(0xffffffffu, cm, o));
            const float m_old = s_m[h];
            const float m_new = fmaxf(m_old, cm);
            float e = (lane < CHUNK) ? __expf(s - m_new) : 0.f;
            float se = e;
#pragma unroll
            for (int o = 16; o; o >>= 1) se += __shfl_xor_sync(0xffffffffu, se, o);
            if (lane < CHUNK) s_e[h][lane] = e;
            if (lane == 0) {
                const float f = __expf(m_old - m_new);
                s_f[h] = f; s_m[h] = m_new;
                s_l[h] = s_l[h] * f + se;
            }
        }
        __syncthreads();

        const float f0 = s_f[0], f1 = s_f[1];
        a00 *= f0; a01 *= f0; a10 *= f1; a11 *= f1;
        const float2* rows2 = (const float2*)rows;
#pragma unroll
        for (int k = 0; k < CHUNK; k++) {
            float2 v = rows2[k * 256 + tid];
            const float e0 = s_e[0][k], e1 = s_e[1][k];
            a00 += e0 * v.x; a01 += e0 * v.y;
            a10 += e1 * v.x; a11 += e1 * v.y;
        }
    }

    const float inv0 = 1.f / s_l[0], inv1 = 1.f / s_l[1];
    __half2* orow = (__half2*)(ctx + (size_t)b * 1024);
    orow[tid]       = __floats2half2_rn(a00 * inv0, a01 * inv0);
    orow[256 + tid] = __floats2half2_rn(a10 * inv1, a11 * inv1);

    if (tid < 64) {
        const float m0 = s_m[0], m1 = s_m[1];
        const float at0 = __expf(s_all[tid]      - m0) * inv0;
        const float at1 = __expf(s_all[64 + tid] - m1) * inv1;
        wout[(size_t)b * 64 + tid] = 0.5f * (at0 + at1);
    }
}

// ---------------- layernorm (fp16 out: GEMM operand) ----------------
__global__ __launch_bounds__(128)
void ln_kernel(const float* __restrict__ x, const float* __restrict__ gam,
               const float* __restrict__ bet, __half* __restrict__ y)
{
    const int b = blockIdx.x, tid = threadIdx.x;
    const float* row = x + (size_t)b * 512;
    float v[4]; float s = 0.f;
#pragma unroll
    for (int j = 0; j < 4; j++) { v[j] = row[tid + 128 * j]; s += v[j]; }
    __shared__ float red[4];
#pragma unroll
    for (int o = 16; o; o >>= 1) s += __shfl_xor_sync(0xffffffffu, s, o);
    if ((tid & 31) == 0) red[tid >> 5] = s;
    __syncthreads();
    s = red[0] + red[1] + red[2] + red[3];
    const float mu = s * (1.f / 512.f);
    float var = 0.f;
#pragma unroll
    for (int j = 0; j < 4; j++) { float d = v[j] - mu; var += d * d; }
    __syncthreads();
#pragma unroll
    for (int o = 16; o; o >>= 1) var += __shfl_xor_sync(0xffffffffu, var, o);
    if ((tid & 31) == 0) red[tid >> 5] = var;
    __syncthreads();
    var = (red[0] + red[1] + red[2] + red[3]) * (1.f / 512.f);
    const float rs = rsqrtf(var + 1e-5f);
#pragma unroll
    for (int j = 0; j < 4; j++) {
        const int c = tid + 128 * j;
        y[(size_t)b * 512 + c] = __float2half_rn(gam[c] * (v[j] - mu) * rs + bet[c]);
    }
}

// ---------------- launch ----------------
extern "C" void kernel_launch(void* const* d_in, const int* in_sizes, int n_in,
                              void* d_out, int out_size)
{
    const float* src  = (const float*)d_in[0];
    const float* seq  = (const float*)d_in[1];
    const void*  mask = d_in[2];
    const float* Wq   = (const float*)d_in[3];
    const float* Wk   = (const float*)d_in[4];
    const float* Wv   = (const float*)d_in[5];
    const float* Wo   = (const float*)d_in[6];
    const float* bo   = (const float*)d_in[7];
    const float* ln_g = (const float*)d_in[8];
    const float* ln_b = (const float*)d_in[9];
    const float* W1   = (const float*)d_in[10];
    const float* b1   = (const float*)d_in[11];
    const float* W2   = (const float*)d_in[12];
    const float* b2   = (const float*)d_in[13];
    float* y    = (float*)d_out;                       // [B, 512]
    float* wout = (float*)d_out + (size_t)B_ * 512;    // [B, 64]

    __half *src_h, *Wq_h, *Wk_h, *Wv_h, *WoT, *W1T, *W2T, *CkT, *CvT, *CTX, *LN, *H1;
    float *QT, *PROJ;
    cudaGetSymbolAddress((void**)&src_h, g_src_h);
    cudaGetSymbolAddress((void**)&Wq_h,  g_Wq_h);
    cudaGetSymbolAddress((void**)&Wk_h,  g_Wk_h);
    cudaGetSymbolAddress((void**)&Wv_h,  g_Wv_h);
    cudaGetSymbolAddress((void**)&WoT,   g_WoT_h);
    cudaGetSymbolAddress((void**)&W1T,   g_W1T_h);
    cudaGetSymbolAddress((void**)&W2T,   g_W2T_h);
    cudaGetSymbolAddress((void**)&CkT,   g_CkT);
    cudaGetSymbolAddress((void**)&CvT,   g_CvT);
    cudaGetSymbolAddress((void**)&QT,    g_QT);
    cudaGetSymbolAddress((void**)&CTX,   g_CTX);
    cudaGetSymbolAddress((void**)&PROJ,  g_PROJ);
    cudaGetSymbolAddress((void**)&LN,    g_LN);
    cudaGetSymbolAddress((void**)&H1,    g_H1);

    cudaFuncSetAttribute(gemm_h_m128,
                         cudaFuncAttributeMaxDynamicSharedMemorySize, GEMM_SMEM_MF(4));
    cudaFuncSetAttribute(gemm_h_m64,
                         cudaFuncAttributeMaxDynamicSharedMemorySize, GEMM_SMEM_MF(2));
    cudaFuncSetAttribute(gemm_h_b4,
                         cudaFuncAttributeMaxDynamicSharedMemorySize, GEMM_SMEM_MF(4));
    cudaFuncSetAttribute(attention_kernel,
                         cudaFuncAttributeMaxDynamicSharedMemorySize, ATTN_SMEM);

    dim3 blk(256);

    detect_mask_kernel<<<1, 256>>>((const unsigned int*)mask);

    // pre-pass: fp16 copies (src, Wq, Wk, Wv)
    C16Batch cb;
    cb.e[0] = { (const float4*)src, (__half2*)src_h, B_ * 512 / 4 };
    cb.e[1] = { (const float4*)Wq,  (__half2*)Wq_h,  512 * 512 / 4 };
    cb.e[2] = { (const float4*)Wk,  (__half2*)Wk_h,  512 * 512 / 4 };
    cb.e[3] = { (const float4*)Wv,  (__half2*)Wv_h,  512 * 512 / 4 };
    cvt16_kernel<<<dim3(132, 1, 4), blk>>>(cb);

    // pre-pass: transposed fp16 (Wo, W1, W2)
    TrBatch tb;
    tb.e[0] = { Wo, WoT, 512, 512 };
    tb.e[1] = { W1, W1T, 1024, 512 };
    tb.e[2] = { W2, W2T, 512, 512 };
    transpose_cvt_kernel<<<dim3(16, 32, 3), blk>>>(tb);

    // precompute: CkT[h512+d][i] = (1/16) sum_k Wk[d,h256+k] Wq[i,h256+k]
    //             CvT[j][h512+i] =        sum_k WoT[j,h256+k] Wv[i,h256+k]
    GemmBatch4 pb;
    pb.e[0] = { Wk_h,       Wq_h,       CkT,                      512,  1.f / 16.f };
    pb.e[1] = { Wk_h + 256, Wq_h + 256, CkT + (size_t)512 * 512,  512,  1.f / 16.f };
    pb.e[2] = { WoT,        Wv_h,       CvT,                      1024, 1.f };
    pb.e[3] = { WoT + 256,  Wv_h + 256, CvT + 512,                1024, 1.f };
    gemm_h_b4<<<dim3(4, 4, 4), blk, GEMM_SMEM_MF(4)>>>(pb);

    // QT = src_h @ CkT^T (fp32 out)
    gemm_h_m128<<<dim3(8, 32), blk, GEMM_SMEM_MF(4)>>>(src_h, 512, nullptr, 0, 0,
                                    CkT, 512, QT, 1024,
                                    nullptr, nullptr, 0, 512, 1.f, 0);
    // flash attention (CTX fp16 out)
    attention_kernel<<<B_, 256, ATTN_SMEM>>>(seq, mask, QT, CTX, wout);
    // PROJ = CTX @ CvT^T + bo + src (fp32 out)
    gemm_h_m64<<<dim3(4, 64), blk, GEMM_SMEM_MF(2)>>>(CTX, 1024, nullptr, 0, 0,
                                    CvT, 1024, PROJ, 512,
                                    bo, src, 512, 1024, 1.f, FLAG_BIAS | FLAG_RESID);
    // LayerNorm (fp16 out)
    ln_kernel<<<B_, 128>>>(PROJ, ln_g, ln_b, LN);
    // H1 = relu([LN | src_h] @ W1T^T + b1) (fp16 out)
    gemm_h_m64<<<dim3(4, 64), blk, GEMM_SMEM_MF(2)>>>(LN, 512, src_h, 512, 512,
                                    W1T, 1024, H1, 512,
                                    b1, nullptr, 0, 1024, 1.f,
                                    FLAG_BIAS | FLAG_RELU | FLAG_OUT16);
    // y = H1 @ W2T^T + b2 (fp32 out)
    gemm_h_m64<<<dim3(4, 64), blk, GEMM_SMEM_MF(2)>>>(H1, 512, nullptr, 0, 0,
                                    W2T, 512, y, 512,
                                    b2, nullptr, 0, 512, 1.f, FLAG_BIAS);
}